// round 2
// baseline (speedup 1.0000x reference)
#include <cuda_runtime.h>
#include <cstdint>
#include <cstddef>

#define NB 8
#define NH 128
#define NW 128
#define CI 256
#define CO 256
#define NL 512
#define NPIX (NB*NH*NW)

#define C_STD  0.0625f
#define C_CONV 0.02946278254943948f
#define C_D1   0.08838834764831845f
#define C_D2   0.04419417382415922f

// ---------------- scratch (static device allocations; no runtime alloc) ----
__device__ float g_s[NB*CI];
__device__ float g_d[NB*CO];
__device__ float g_xs[(size_t)NPIX*CI];      // modulated, tf32-rounded input
__device__ float g_wc[9*CI*CO];              // scaled tf32 conv weights
__device__ float g_w1[CO*4*CO];              // scaled tf32 D1 weights
__device__ float g_w2[4*CO*CO];              // scaled tf32 D2 weights
__device__ float g_y[(size_t)NPIX*CO];       // conv output (post-lrelu, tf32)
__device__ float g_h[(size_t)NPIX*4*CO];     // D1 output (post-lrelu, tf32)

// ---------------- helpers --------------------------------------------------
__device__ __forceinline__ float to_tf32(float x){
    float r; asm("cvt.rna.tf32.f32 %0, %1;" : "=f"(r) : "f"(x)); return r;
}
__device__ __forceinline__ float lrelu(float x){ return x > 0.f ? x : 0.2f*x; }

__device__ __forceinline__ void mma8(float c[4], const uint32_t a[4], const uint32_t b[2]){
    asm volatile("mma.sync.aligned.m16n8k8.row.col.f32.tf32.tf32.f32 "
        "{%0,%1,%2,%3}, {%4,%5,%6,%7}, {%8,%9}, {%0,%1,%2,%3};\n"
        : "+f"(c[0]), "+f"(c[1]), "+f"(c[2]), "+f"(c[3])
        : "r"(a[0]), "r"(a[1]), "r"(a[2]), "r"(a[3]), "r"(b[0]), "r"(b[1]));
}
__device__ __forceinline__ void cp16(uint32_t d, const void* s, int nbytes){
    asm volatile("cp.async.ca.shared.global [%0], [%1], 16, %2;\n"
                 :: "r"(d), "l"(s), "r"(nbytes));
}
__device__ __forceinline__ void cp_commit(){ asm volatile("cp.async.commit_group;\n"); }
template<int N> __device__ __forceinline__ void cp_wait(){
    asm volatile("cp.async.wait_group %0;\n" :: "n"(N));
}

// ---------------- tile layout ----------------------------------------------
struct Tiles {
    float A[128][36];    // [M][K] padded (36: conflict-free quad access)
    float Bm[32][136];   // [K][N] padded (136 -> 8k+dn distinct banks)
};

__device__ __forceinline__ void compute_tile(const Tiles& t, float acc[2][8][4],
                                             int wm, int wn, int qr, int qc){
#pragma unroll
    for (int kk = 0; kk < 4; kk++){
        uint32_t a[2][4];
#pragma unroll
        for (int mt = 0; mt < 2; mt++){
            int row = wm*32 + mt*16 + qr;
            a[mt][0] = __float_as_uint(t.A[row  ][kk*8+qc  ]);
            a[mt][1] = __float_as_uint(t.A[row+8][kk*8+qc  ]);
            a[mt][2] = __float_as_uint(t.A[row  ][kk*8+qc+4]);
            a[mt][3] = __float_as_uint(t.A[row+8][kk*8+qc+4]);
        }
        uint32_t b[8][2];
#pragma unroll
        for (int nt = 0; nt < 8; nt++){
            int n = wn*64 + nt*8 + qr;
            b[nt][0] = __float_as_uint(t.Bm[kk*8+qc  ][n]);
            b[nt][1] = __float_as_uint(t.Bm[kk*8+qc+4][n]);
        }
#pragma unroll
        for (int mt = 0; mt < 2; mt++)
#pragma unroll
            for (int nt = 0; nt < 8; nt++)
                mma8(acc[mt][nt], a[mt], b[nt]);
    }
}

// ---------------- prep kernels ---------------------------------------------
__global__ void s_kernel(const float* __restrict__ latent,
                         const float* __restrict__ stdW,
                         const float* __restrict__ stdb){
    int b = blockIdx.x, i = threadIdx.x;
    float acc = 0.f;
    for (int l = 0; l < NL; l++) acc += latent[b*NL+l] * stdW[l*CI+i];
    g_s[b*CI+i] = acc * C_STD + stdb[i];
}

__global__ void d_kernel(const float* __restrict__ cw){
    int b = blockIdx.x, o = threadIdx.x;
    float acc = 0.f;
    for (int i = 0; i < CI; i++){
        float w2 = 0.f;
#pragma unroll
        for (int k = 0; k < 9; k++){
            float wv = cw[(size_t)(k*CI + i)*CO + o];
            w2 += wv*wv;
        }
        float sv = g_s[b*CI+i];
        acc += w2 * sv * sv;
    }
    g_d[b*CO+o] = rsqrtf(acc * (C_CONV*C_CONV) + 1e-8f);
}

__global__ void mod_kernel(const float* __restrict__ data){
    size_t idx = ((size_t)blockIdx.x * blockDim.x + threadIdx.x) * 4;
    float4 x = *(const float4*)(data + idx);
    int c = (int)(idx & (CI-1));
    int b = (int)(idx >> 22);         // / (128*128*256)
    float4 s = *(const float4*)(g_s + b*CI + c);
    float4 r;
    r.x = to_tf32(x.x*s.x); r.y = to_tf32(x.y*s.y);
    r.z = to_tf32(x.z*s.z); r.w = to_tf32(x.w*s.w);
    *(float4*)(g_xs + idx) = r;
}

__global__ void wscale_kernel(const float* __restrict__ src, float* __restrict__ dst,
                              float sc, int n4){
    int idx = blockIdx.x * blockDim.x + threadIdx.x;
    if (idx < n4){
        float4 v = *(const float4*)(src + (size_t)idx*4);
        float4 r;
        r.x = to_tf32(v.x*sc); r.y = to_tf32(v.y*sc);
        r.z = to_tf32(v.z*sc); r.w = to_tf32(v.w*sc);
        *(float4*)(dst + (size_t)idx*4) = r;
    }
}

// ---------------- conv (implicit GEMM) -------------------------------------
__device__ __forceinline__ void issue_conv(Tiles* t, int b, int h, int n0,
                                           int kc, int tid){
    int ktap = kc >> 3, ci0 = (kc & 7) * 32;
    int dh = ktap/3 - 1, dw = ktap%3 - 1;
    int hp = h + dh;
    bool hv = (unsigned)hp < NH;
#pragma unroll
    for (int j = 0; j < 4; j++){
        int lin = tid + j*256;
        int wrow = lin >> 3, c4 = (lin & 7) * 4;
        int wp = wrow + dw;
        bool v = hv && ((unsigned)wp < NW);
        const float* src = v ? (g_xs + ((size_t)((b*NH+hp)*NW + wp))*CI + ci0 + c4)
                             : (const float*)g_xs;
        cp16((uint32_t)__cvta_generic_to_shared(&t->A[wrow][c4]), src, v ? 16 : 0);
        int kk = lin >> 5, n4 = (lin & 31) * 4;
        cp16((uint32_t)__cvta_generic_to_shared(&t->Bm[kk][n4]),
             g_wc + (size_t)((ktap*CI + ci0 + kk)*CO) + n0 + n4, 16);
    }
    cp_commit();
}

__global__ void __launch_bounds__(256,2) conv_kernel(
    const float* __restrict__ bias, const float* __restrict__ noise,
    const float* __restrict__ ncoef)
{
    extern __shared__ Tiles tiles[];
    int tid = threadIdx.x;
    int bh = blockIdx.y; int b = bh >> 7, h = bh & 127;
    int n0 = blockIdx.x * 128;
    int wid = tid >> 5, lane = tid & 31;
    int wm = wid >> 1, wn = wid & 1, qr = lane >> 2, qc = lane & 3;

    float acc[2][8][4];
#pragma unroll
    for (int i = 0; i < 2; i++)
#pragma unroll
        for (int j = 0; j < 8; j++)
#pragma unroll
            for (int k = 0; k < 4; k++) acc[i][j][k] = 0.f;

    const int NK = 72;
    issue_conv(&tiles[0], b, h, n0, 0, tid);
#pragma unroll 1
    for (int kc = 0; kc < NK; kc++){
        if (kc + 1 < NK){ issue_conv(&tiles[(kc+1)&1], b, h, n0, kc+1, tid); cp_wait<1>(); }
        else            { cp_wait<0>(); }
        __syncthreads();
        compute_tile(tiles[kc&1], acc, wm, wn, qr, qc);
        __syncthreads();
    }

    size_t prow = (size_t)(b*NH + h) * NW;
#pragma unroll
    for (int mt = 0; mt < 2; mt++){
#pragma unroll
        for (int nt = 0; nt < 8; nt++){
            int col = n0 + wn*64 + nt*8 + 2*qc;
            float d0 = g_d[b*CO+col], d1 = g_d[b*CO+col+1];
            float b0 = bias[col], b1 = bias[col+1];
            float nc0 = ncoef[col], nc1 = ncoef[col+1];
#pragma unroll
            for (int r2 = 0; r2 < 2; r2++){
                int w = wm*32 + mt*16 + qr + r2*8;
                size_t p = prow + w;
                float2 nz = *(const float2*)(noise + p*CO + col);
                float v0 = acc[mt][nt][r2*2+0]*d0 + b0 + nz.x*nc0;
                float v1 = acc[mt][nt][r2*2+1]*d1 + b1 + nz.y*nc1;
                v0 = to_tf32(lrelu(v0));
                v1 = to_tf32(lrelu(v1));
                *(float2*)(g_y + p*CO + col) = make_float2(v0, v1);
            }
        }
    }
}

// ---------------- generic GEMM (A,B pre-rounded tf32) ----------------------
template<int K, int N>
__device__ __forceinline__ void issue_gemm(Tiles* t, const float* A, const float* Bw,
                                           size_t m0, int n0, int kc, int tid){
#pragma unroll
    for (int j = 0; j < 4; j++){
        int lin = tid + j*256;
        int row = lin >> 3, c4 = (lin & 7) * 4;
        cp16((uint32_t)__cvta_generic_to_shared(&t->A[row][c4]),
             A + (m0 + row)*(size_t)K + (size_t)kc*32 + c4, 16);
        int kk = lin >> 5, n4 = (lin & 31) * 4;
        cp16((uint32_t)__cvta_generic_to_shared(&t->Bm[kk][n4]),
             Bw + (size_t)(kc*32 + kk)*N + n0 + n4, 16);
    }
    cp_commit();
}

template<int K, int N, bool ROUND>
__global__ void __launch_bounds__(256,2) gemm_kernel(
    const float* __restrict__ A, const float* __restrict__ Bw,
    const float* __restrict__ bias, float* __restrict__ out)
{
    extern __shared__ Tiles tiles[];
    int tid = threadIdx.x;
    size_t m0 = (size_t)blockIdx.y * 128;
    int n0 = blockIdx.x * 128;
    int wid = tid >> 5, lane = tid & 31;
    int wm = wid >> 1, wn = wid & 1, qr = lane >> 2, qc = lane & 3;

    float acc[2][8][4];
#pragma unroll
    for (int i = 0; i < 2; i++)
#pragma unroll
        for (int j = 0; j < 8; j++)
#pragma unroll
            for (int k = 0; k < 4; k++) acc[i][j][k] = 0.f;

    const int NK = K/32;
    issue_gemm<K,N>(&tiles[0], A, Bw, m0, n0, 0, tid);
#pragma unroll 1
    for (int kc = 0; kc < NK; kc++){
        if (kc + 1 < NK){ issue_gemm<K,N>(&tiles[(kc+1)&1], A, Bw, m0, n0, kc+1, tid); cp_wait<1>(); }
        else            { cp_wait<0>(); }
        __syncthreads();
        compute_tile(tiles[kc&1], acc, wm, wn, qr, qc);
        __syncthreads();
    }

#pragma unroll
    for (int mt = 0; mt < 2; mt++){
#pragma unroll
        for (int nt = 0; nt < 8; nt++){
            int col = n0 + wn*64 + nt*8 + 2*qc;
            float b0 = bias[col], b1 = bias[col+1];
#pragma unroll
            for (int r2 = 0; r2 < 2; r2++){
                size_t m = m0 + wm*32 + mt*16 + qr + r2*8;
                float v0 = lrelu(acc[mt][nt][r2*2+0] + b0);
                float v1 = lrelu(acc[mt][nt][r2*2+1] + b1);
                if (ROUND){ v0 = to_tf32(v0); v1 = to_tf32(v1); }
                *(float2*)(out + m*(size_t)N + col) = make_float2(v0, v1);
            }
        }
    }
}

// ---------------- launch ----------------------------------------------------
extern "C" void kernel_launch(void* const* d_in, const int* in_sizes, int n_in,
                              void* d_out, int out_size){
    const float* data   = (const float*)d_in[0];
    const float* latent = (const float*)d_in[1];
    const float* noise  = (const float*)d_in[2];
    const float* stdW   = (const float*)d_in[3];
    const float* stdb   = (const float*)d_in[4];
    const float* convw  = (const float*)d_in[5];
    const float* bias   = (const float*)d_in[6];
    const float* ncoef  = (const float*)d_in[7];
    const float* d1w    = (const float*)d_in[8];
    const float* d1b    = (const float*)d_in[9];
    const float* d2w    = (const float*)d_in[10];
    const float* d2b    = (const float*)d_in[11];
    float* out = (float*)d_out;

    void *p_wc, *p_w1, *p_w2, *p_y, *p_h;
    cudaGetSymbolAddress(&p_wc, g_wc);
    cudaGetSymbolAddress(&p_w1, g_w1);
    cudaGetSymbolAddress(&p_w2, g_w2);
    cudaGetSymbolAddress(&p_y,  g_y);
    cudaGetSymbolAddress(&p_h,  g_h);

    int smem = (int)sizeof(Tiles) * 2;  // 71680 B, double-buffered
    cudaFuncSetAttribute(conv_kernel, cudaFuncAttributeMaxDynamicSharedMemorySize, smem);
    cudaFuncSetAttribute(gemm_kernel<256,1024,true>,  cudaFuncAttributeMaxDynamicSharedMemorySize, smem);
    cudaFuncSetAttribute(gemm_kernel<1024,256,false>, cudaFuncAttributeMaxDynamicSharedMemorySize, smem);

    s_kernel<<<NB, CI>>>(latent, stdW, stdb);
    d_kernel<<<NB, CO>>>(convw);
    mod_kernel<<<32768, 256>>>(data);
    wscale_kernel<<<(9*CI*CO/4 + 255)/256, 256>>>(convw, (float*)p_wc, C_CONV, 9*CI*CO/4);
    wscale_kernel<<<(CO*4*CO/4 + 255)/256, 256>>>(d1w,  (float*)p_w1, C_D1,  CO*4*CO/4);
    wscale_kernel<<<(4*CO*CO/4 + 255)/256, 256>>>(d2w,  (float*)p_w2, C_D2,  4*CO*CO/4);

    conv_kernel<<<dim3(2,1024), 256, smem>>>(bias, noise, ncoef);
    gemm_kernel<256,1024,true ><<<dim3(8,1024), 256, smem>>>((const float*)p_y, (const float*)p_w1, d1b, (float*)p_h);
    gemm_kernel<1024,256,false><<<dim3(2,1024), 256, smem>>>((const float*)p_h, (const float*)p_w2, d2b, out);
}

// round 4
// speedup vs baseline: 2.2438x; 2.2438x over previous
#include <cuda_runtime.h>
#include <cuda_fp16.h>
#include <cstdint>
#include <cstddef>

#define NB 8
#define CI 256
#define CO 256
#define NL 512
#define NPIX (8*128*128)

#define C_STD  0.0625f
#define C_CONV 0.02946278254943948f
#define C_D1   0.08838834764831845f
#define C_D2   0.04419417382415922f

// ---------------- scratch --------------------------------------------------
__device__ float  g_s[NB*CI];
__device__ float  g_d[NB*CO];
__device__ __half g_xs[(size_t)NPIX*CI];       // modulated input, fp16
__device__ __half g_wcT[9*CO*CI];              // conv w [tap][co][ci], scaled
__device__ __half g_w1T[4*CO*CO];              // D1 w [n=1024][k=256]
__device__ __half g_w2T[(size_t)CO*4*CO];      // D2 w [n=256][k=1024]
__device__ __half g_y[(size_t)NPIX*CO];        // conv out (post-lrelu)
__device__ __half g_h[(size_t)NPIX*4*CO];      // D1 out (post-lrelu)

// ---------------- helpers --------------------------------------------------
__device__ __forceinline__ float lrelu(float x){ return x > 0.f ? x : 0.2f*x; }

__device__ __forceinline__ void mma16(float c[4], const uint32_t a[4], const uint32_t b[2]){
    asm volatile("mma.sync.aligned.m16n8k16.row.col.f32.f16.f16.f32 "
        "{%0,%1,%2,%3}, {%4,%5,%6,%7}, {%8,%9}, {%0,%1,%2,%3};\n"
        : "+f"(c[0]), "+f"(c[1]), "+f"(c[2]), "+f"(c[3])
        : "r"(a[0]), "r"(a[1]), "r"(a[2]), "r"(a[3]), "r"(b[0]), "r"(b[1]));
}
__device__ __forceinline__ void cp16(uint32_t d, const void* s, int nbytes){
    asm volatile("cp.async.ca.shared.global [%0], [%1], 16, %2;\n"
                 :: "r"(d), "l"(s), "r"(nbytes));
}
__device__ __forceinline__ void cp_commit(){ asm volatile("cp.async.commit_group;\n"); }
template<int N> __device__ __forceinline__ void cp_wait(){
    asm volatile("cp.async.wait_group %0;\n" :: "n"(N));
}

// ---------------- tile layout ----------------------------------------------
// A: [M=128][K=32] halves, row stride 40 halves (80 B) -> conflict-free half2
// Bt: [N=128][K=32] halves (weights pre-transposed to [N][K])
struct Tiles {
    __half A[128][40];
    __half Bt[128][40];
};

__device__ __forceinline__ uint32_t ldh2(const __half* p){
    return *(const uint32_t*)p;
}

__device__ __forceinline__ void compute_tile(const Tiles& t, float acc[2][8][4],
                                             int wm, int wn, int qr, int qc){
#pragma unroll
    for (int kk = 0; kk < 2; kk++){
        int k0 = kk*16 + 2*qc;
        uint32_t a[2][4];
#pragma unroll
        for (int mt = 0; mt < 2; mt++){
            int row = wm*32 + mt*16 + qr;
            a[mt][0] = ldh2(&t.A[row  ][k0  ]);
            a[mt][1] = ldh2(&t.A[row+8][k0  ]);
            a[mt][2] = ldh2(&t.A[row  ][k0+8]);
            a[mt][3] = ldh2(&t.A[row+8][k0+8]);
        }
        uint32_t b[8][2];
#pragma unroll
        for (int nt = 0; nt < 8; nt++){
            int n = wn*64 + nt*8 + qr;
            b[nt][0] = ldh2(&t.Bt[n][k0  ]);
            b[nt][1] = ldh2(&t.Bt[n][k0+8]);
        }
#pragma unroll
        for (int mt = 0; mt < 2; mt++)
#pragma unroll
            for (int nt = 0; nt < 8; nt++)
                mma16(acc[mt][nt], a[mt], b[nt]);
    }
}

// ---------------- prep kernels ---------------------------------------------
__global__ void s_kernel(const float* __restrict__ latent,
                         const float* __restrict__ stdW,
                         const float* __restrict__ stdb){
    int b = blockIdx.x, i = threadIdx.x;
    float acc = 0.f;
    for (int l = 0; l < NL; l++) acc += latent[b*NL+l] * stdW[l*CI+i];
    g_s[b*CI+i] = acc * C_STD + stdb[i];
}

__global__ void d_kernel(const float* __restrict__ cw){
    int b = blockIdx.x, o = threadIdx.x;
    float acc = 0.f;
    for (int i = 0; i < CI; i++){
        float w2 = 0.f;
#pragma unroll
        for (int k = 0; k < 9; k++){
            float wv = cw[(size_t)(k*CI + i)*CO + o];
            w2 += wv*wv;
        }
        float sv = g_s[b*CI+i];
        acc += w2 * sv * sv;
    }
    g_d[b*CO+o] = rsqrtf(acc * (C_CONV*C_CONV) + 1e-8f);
}

__global__ void mod_kernel(const float* __restrict__ data){
    size_t idx = ((size_t)blockIdx.x * blockDim.x + threadIdx.x) * 4;
    float4 x = *(const float4*)(data + idx);
    int c = (int)(idx & (CI-1));
    int b = (int)(idx >> 22);
    float4 s = *(const float4*)(g_s + b*CI + c);
    __half2 h0 = __floats2half2_rn(x.x*s.x, x.y*s.y);
    __half2 h1 = __floats2half2_rn(x.z*s.z, x.w*s.w);
    uint2 pk; pk.x = *(uint32_t*)&h0; pk.y = *(uint32_t*)&h1;
    *(uint2*)(g_xs + idx) = pk;
}

// transpose+scale to half: dst[z][c][r] = half(src[z][r][c]*sc)
__global__ void tscaleh(const float* __restrict__ src, __half* __restrict__ dst,
                        int R, int C, float sc){
    __shared__ float t[32][33];
    size_t base = (size_t)blockIdx.z * R * C;
    int r0 = blockIdx.y*32, c0 = blockIdx.x*32;
    int x = threadIdx.x, y = threadIdx.y;   // 32 x 8
#pragma unroll
    for (int i = 0; i < 32; i += 8)
        t[y+i][x] = src[base + (size_t)(r0+y+i)*C + c0+x];
    __syncthreads();
#pragma unroll
    for (int i = 0; i < 32; i += 8)
        dst[base + (size_t)(c0+y+i)*R + r0+x] = __float2half_rn(t[x][y+i]*sc);
}

// ---------------- conv (implicit GEMM) -------------------------------------
__device__ __forceinline__ void issue_conv(Tiles* t, int b, int h, int n0,
                                           int kc, int tid){
    int tap = kc >> 3, ci0 = (kc & 7) * 32;
    int dh = tap/3 - 1, dw = tap%3 - 1;
    int hp = h + dh;
    bool hv = (unsigned)hp < 128u;
#pragma unroll
    for (int j = 0; j < 2; j++){
        int lin = tid + j*256;
        int r = lin >> 2, ch = lin & 3;          // r: 0..127, ch: 0..3 (8 halves)
        int wp = r + dw;
        bool v = hv && ((unsigned)wp < 128u);
        const __half* src = v ? (g_xs + ((size_t)((b*128+hp)*128 + wp))*CI + ci0 + ch*8)
                              : (const __half*)g_xs;
        cp16((uint32_t)__cvta_generic_to_shared(&t->A[r][ch*8]), src, v ? 16 : 0);
        cp16((uint32_t)__cvta_generic_to_shared(&t->Bt[r][ch*8]),
             g_wcT + ((size_t)(tap*256 + n0 + r))*CI + ci0 + ch*8, 16);
    }
    cp_commit();
}

__global__ void __launch_bounds__(256,2) conv_kernel(
    const float* __restrict__ bias, const float* __restrict__ noise,
    const float* __restrict__ ncoef)
{
    extern __shared__ Tiles tiles[];
    int tid = threadIdx.x;
    int bh = blockIdx.y; int b = bh >> 7, h = bh & 127;
    int n0 = blockIdx.x * 128;
    int wid = tid >> 5, lane = tid & 31;
    int wm = wid >> 1, wn = wid & 1, qr = lane >> 2, qc = lane & 3;

    float acc[2][8][4];
#pragma unroll
    for (int i = 0; i < 2; i++)
#pragma unroll
        for (int j = 0; j < 8; j++)
#pragma unroll
            for (int k = 0; k < 4; k++) acc[i][j][k] = 0.f;

    const int NK = 72;
    issue_conv(&tiles[0], b, h, n0, 0, tid);
#pragma unroll 1
    for (int kc = 0; kc < NK; kc++){
        if (kc + 1 < NK){ issue_conv(&tiles[(kc+1)&1], b, h, n0, kc+1, tid); cp_wait<1>(); }
        else            { cp_wait<0>(); }
        __syncthreads();
        compute_tile(tiles[kc&1], acc, wm, wn, qr, qc);
        __syncthreads();
    }

    size_t prow = (size_t)(b*128 + h) * 128;
#pragma unroll
    for (int mt = 0; mt < 2; mt++){
#pragma unroll
        for (int nt = 0; nt < 8; nt++){
            int col = n0 + wn*64 + nt*8 + 2*qc;
            float d0 = g_d[b*CO+col], d1 = g_d[b*CO+col+1];
            float b0 = bias[col], b1 = bias[col+1];
            float nc0 = ncoef[col], nc1 = ncoef[col+1];
#pragma unroll
            for (int r2 = 0; r2 < 2; r2++){
                int w = wm*32 + mt*16 + qr + r2*8;
                size_t p = prow + w;
                float2 nz = *(const float2*)(noise + p*CO + col);
                float v0 = lrelu(acc[mt][nt][r2*2+0]*d0 + b0 + nz.x*nc0);
                float v1 = lrelu(acc[mt][nt][r2*2+1]*d1 + b1 + nz.y*nc1);
                __half2 hv = __floats2half2_rn(v0, v1);
                *(uint32_t*)(g_y + p*CO + col) = *(uint32_t*)&hv;
            }
        }
    }
}

// ---------------- generic GEMM (A [M][K], B [N][K], both fp16) -------------
template<int K>
__device__ __forceinline__ void issue_gemm(Tiles* t, const __half* A, const __half* Bw,
                                           size_t m0, int n0, int kc, int tid){
#pragma unroll
    for (int j = 0; j < 2; j++){
        int lin = tid + j*256;
        int r = lin >> 2, ch = lin & 3;
        cp16((uint32_t)__cvta_generic_to_shared(&t->A[r][ch*8]),
             A + (m0 + r)*(size_t)K + kc*32 + ch*8, 16);
        cp16((uint32_t)__cvta_generic_to_shared(&t->Bt[r][ch*8]),
             Bw + (size_t)(n0 + r)*K + kc*32 + ch*8, 16);
    }
    cp_commit();
}

template<int K, int N, bool HALF_OUT>
__global__ void __launch_bounds__(256,2) gemm_kernel(
    const __half* __restrict__ A, const __half* __restrict__ Bw,
    const float* __restrict__ bias, void* __restrict__ outv)
{
    extern __shared__ Tiles tiles[];
    int tid = threadIdx.x;
    size_t m0 = (size_t)blockIdx.y * 128;
    int n0 = blockIdx.x * 128;
    int wid = tid >> 5, lane = tid & 31;
    int wm = wid >> 1, wn = wid & 1, qr = lane >> 2, qc = lane & 3;

    float acc[2][8][4];
#pragma unroll
    for (int i = 0; i < 2; i++)
#pragma unroll
        for (int j = 0; j < 8; j++)
#pragma unroll
            for (int k = 0; k < 4; k++) acc[i][j][k] = 0.f;

    const int NK = K/32;
    issue_gemm<K>(&tiles[0], A, Bw, m0, n0, 0, tid);
#pragma unroll 1
    for (int kc = 0; kc < NK; kc++){
        if (kc + 1 < NK){ issue_gemm<K>(&tiles[(kc+1)&1], A, Bw, m0, n0, kc+1, tid); cp_wait<1>(); }
        else            { cp_wait<0>(); }
        __syncthreads();
        compute_tile(tiles[kc&1], acc, wm, wn, qr, qc);
        __syncthreads();
    }

#pragma unroll
    for (int mt = 0; mt < 2; mt++){
#pragma unroll
        for (int nt = 0; nt < 8; nt++){
            int col = n0 + wn*64 + nt*8 + 2*qc;
            float b0 = bias[col], b1 = bias[col+1];
#pragma unroll
            for (int r2 = 0; r2 < 2; r2++){
                size_t m = m0 + wm*32 + mt*16 + qr + r2*8;
                float v0 = lrelu(acc[mt][nt][r2*2+0] + b0);
                float v1 = lrelu(acc[mt][nt][r2*2+1] + b1);
                if (HALF_OUT){
                    __half2 hv = __floats2half2_rn(v0, v1);
                    *(uint32_t*)((__half*)outv + m*(size_t)N + col) = *(uint32_t*)&hv;
                } else {
                    *(float2*)((float*)outv + m*(size_t)N + col) = make_float2(v0, v1);
                }
            }
        }
    }
}

// ---------------- launch ----------------------------------------------------
extern "C" void kernel_launch(void* const* d_in, const int* in_sizes, int n_in,
                              void* d_out, int out_size){
    const float* data   = (const float*)d_in[0];
    const float* latent = (const float*)d_in[1];
    const float* noise  = (const float*)d_in[2];
    const float* stdW   = (const float*)d_in[3];
    const float* stdb   = (const float*)d_in[4];
    const float* convw  = (const float*)d_in[5];
    const float* bias   = (const float*)d_in[6];
    const float* ncoef  = (const float*)d_in[7];
    const float* d1w    = (const float*)d_in[8];
    const float* d1b    = (const float*)d_in[9];
    const float* d2w    = (const float*)d_in[10];
    const float* d2b    = (const float*)d_in[11];
    float* out = (float*)d_out;

    void *p_wc, *p_w1, *p_w2, *p_y, *p_h;
    cudaGetSymbolAddress(&p_wc, g_wcT);
    cudaGetSymbolAddress(&p_w1, g_w1T);
    cudaGetSymbolAddress(&p_w2, g_w2T);
    cudaGetSymbolAddress(&p_y,  g_y);
    cudaGetSymbolAddress(&p_h,  g_h);

    int smem = (int)sizeof(Tiles) * 2;   // 40960 B double-buffered
    cudaFuncSetAttribute(conv_kernel, cudaFuncAttributeMaxDynamicSharedMemorySize, smem);
    cudaFuncSetAttribute(gemm_kernel<256,1024,true>,  cudaFuncAttributeMaxDynamicSharedMemorySize, smem);
    cudaFuncSetAttribute(gemm_kernel<1024,256,false>, cudaFuncAttributeMaxDynamicSharedMemorySize, smem);

    s_kernel<<<NB, CI>>>(latent, stdW, stdb);
    d_kernel<<<NB, CO>>>(convw);
    mod_kernel<<<32768, 256>>>(data);
    // conv w: per tap transpose [ci][co] -> [co][ci]
    tscaleh<<<dim3(8,8,9),  dim3(32,8)>>>(convw, (__half*)p_wc, 256, 256,  C_CONV);
    // D1 w: [256][1024] -> [1024][256]
    tscaleh<<<dim3(32,8,1), dim3(32,8)>>>(d1w,   (__half*)p_w1, 256, 1024, C_D1);
    // D2 w: [1024][256] -> [256][1024]
    tscaleh<<<dim3(8,32,1), dim3(32,8)>>>(d2w,   (__half*)p_w2, 1024, 256, C_D2);

    conv_kernel<<<dim3(2,1024), 256, smem>>>(bias, noise, ncoef);
    gemm_kernel<256,1024,true ><<<dim3(8,1024), 256, smem>>>(
        (const __half*)p_y, (const __half*)p_w1, d1b, p_h);
    gemm_kernel<1024,256,false><<<dim3(2,1024), 256, smem>>>(
        (const __half*)p_h, (const __half*)p_w2, d2b, (void*)out);
}

// round 5
// speedup vs baseline: 2.2720x; 1.0126x over previous
#include <cuda_runtime.h>
#include <cuda_fp16.h>
#include <cstdint>
#include <cstddef>

#define NB 8
#define CI 256
#define CO 256
#define NL 512
#define NPIX (8*128*128)

#define C_STD  0.0625f
#define C_CONV 0.02946278254943948f
#define C_D1   0.08838834764831845f
#define C_D2   0.04419417382415922f

// ---------------- scratch --------------------------------------------------
__device__ float  g_s[NB*CI];
__device__ float  g_d[NB*CO];
__device__ __half g_xs[(size_t)NPIX*CI];       // modulated input, fp16
__device__ __half g_wcT[9*CO*CI];              // conv w [tap][co][ci], scaled
__device__ __half g_w1T[4*CO*CO];              // D1 w [n=1024][k=256]
__device__ __half g_w2T[(size_t)CO*4*CO];      // D2 w [n=256][k=1024]
__device__ __half g_y[(size_t)NPIX*CO];        // conv out (post-lrelu)
__device__ __half g_h[(size_t)NPIX*4*CO];      // D1 out (post-lrelu)

// ---------------- helpers --------------------------------------------------
__device__ __forceinline__ float lrelu(float x){ return x > 0.f ? x : 0.2f*x; }

__device__ __forceinline__ void mma16(float c[4], const uint32_t a[4], const uint32_t b[2]){
    asm volatile("mma.sync.aligned.m16n8k16.row.col.f32.f16.f16.f32 "
        "{%0,%1,%2,%3}, {%4,%5,%6,%7}, {%8,%9}, {%0,%1,%2,%3};\n"
        : "+f"(c[0]), "+f"(c[1]), "+f"(c[2]), "+f"(c[3])
        : "r"(a[0]), "r"(a[1]), "r"(a[2]), "r"(a[3]), "r"(b[0]), "r"(b[1]));
}
__device__ __forceinline__ void cp16(uint32_t d, const void* s, int nbytes){
    asm volatile("cp.async.ca.shared.global [%0], [%1], 16, %2;\n"
                 :: "r"(d), "l"(s), "r"(nbytes));
}
__device__ __forceinline__ void cp_commit(){ asm volatile("cp.async.commit_group;\n"); }
template<int N> __device__ __forceinline__ void cp_wait(){
    asm volatile("cp.async.wait_group %0;\n" :: "n"(N));
}

// ---------------- tile layout ----------------------------------------------
struct Tiles {
    __half A[128][40];    // [M][K=32], 80B row stride -> conflict-free half2
    __half Bt[128][40];   // [N][K=32], weights pre-transposed to [N][K]
};

__device__ __forceinline__ uint32_t ldh2(const __half* p){
    return *(const uint32_t*)p;
}

__device__ __forceinline__ void compute_tile(const Tiles& t, float acc[2][8][4],
                                             int wm, int wn, int qr, int qc){
#pragma unroll
    for (int kk = 0; kk < 2; kk++){
        int k0 = kk*16 + 2*qc;
        uint32_t a[2][4];
#pragma unroll
        for (int mt = 0; mt < 2; mt++){
            int row = wm*32 + mt*16 + qr;
            a[mt][0] = ldh2(&t.A[row  ][k0  ]);
            a[mt][1] = ldh2(&t.A[row+8][k0  ]);
            a[mt][2] = ldh2(&t.A[row  ][k0+8]);
            a[mt][3] = ldh2(&t.A[row+8][k0+8]);
        }
        uint32_t b[8][2];
#pragma unroll
        for (int nt = 0; nt < 8; nt++){
            int n = wn*64 + nt*8 + qr;
            b[nt][0] = ldh2(&t.Bt[n][k0  ]);
            b[nt][1] = ldh2(&t.Bt[n][k0+8]);
        }
#pragma unroll
        for (int mt = 0; mt < 2; mt++)
#pragma unroll
            for (int nt = 0; nt < 8; nt++)
                mma16(acc[mt][nt], a[mt], b[nt]);
    }
}

// ---------------- prep kernels ---------------------------------------------
__global__ void s_kernel(const float* __restrict__ latent,
                         const float* __restrict__ stdW,
                         const float* __restrict__ stdb){
    int b = blockIdx.x, i = threadIdx.x;
    float acc = 0.f;
    for (int l = 0; l < NL; l++) acc += latent[b*NL+l] * stdW[l*CI+i];
    g_s[b*CI+i] = acc * C_STD + stdb[i];
}

__global__ void d_kernel(const float* __restrict__ cw){
    int b = blockIdx.x, o = threadIdx.x;
    float acc = 0.f;
    for (int i = 0; i < CI; i++){
        float w2 = 0.f;
#pragma unroll
        for (int k = 0; k < 9; k++){
            float wv = cw[(size_t)(k*CI + i)*CO + o];
            w2 += wv*wv;
        }
        float sv = g_s[b*CI+i];
        acc += w2 * sv * sv;
    }
    g_d[b*CO+o] = rsqrtf(acc * (C_CONV*C_CONV) + 1e-8f);
}

__global__ void mod_kernel(const float* __restrict__ data){
    size_t idx = ((size_t)blockIdx.x * blockDim.x + threadIdx.x) * 4;
    float4 x = *(const float4*)(data + idx);
    int c = (int)(idx & (CI-1));
    int b = (int)(idx >> 22);
    float4 s = *(const float4*)(g_s + b*CI + c);
    __half2 h0 = __floats2half2_rn(x.x*s.x, x.y*s.y);
    __half2 h1 = __floats2half2_rn(x.z*s.z, x.w*s.w);
    uint2 pk; pk.x = *(uint32_t*)&h0; pk.y = *(uint32_t*)&h1;
    *(uint2*)(g_xs + idx) = pk;
}

// transpose+scale core: dst[c][r] = half(src[r][c]*sc), 32x32 tile at (r0,c0)
__device__ __forceinline__ void tblock(const float* src, __half* dst,
                                       int R, int C, float sc, int r0, int c0){
    __shared__ float t[32][33];
    int x = threadIdx.x, y = threadIdx.y;   // 32 x 8
#pragma unroll
    for (int i = 0; i < 32; i += 8)
        t[y+i][x] = src[(size_t)(r0+y+i)*C + c0+x];
    __syncthreads();
#pragma unroll
    for (int i = 0; i < 32; i += 8)
        dst[(size_t)(c0+y+i)*R + r0+x] = __float2half_rn(t[x][y+i]*sc);
}

// conv weights: 9 taps, transpose [ci][co] -> [co][ci]; grid (8,8,9)
__global__ void tscale_conv(const float* __restrict__ src, __half* __restrict__ dst){
    size_t off = (size_t)blockIdx.z * 256 * 256;
    tblock(src + off, dst + off, 256, 256, C_CONV, blockIdx.y*32, blockIdx.x*32);
}
// D1 + D2 weights fused; grid (32,8,2)
__global__ void tscale_d12(const float* __restrict__ d1w, const float* __restrict__ d2w,
                           __half* __restrict__ w1, __half* __restrict__ w2){
    if (blockIdx.z == 0){
        tblock(d1w, w1, 256, 1024, C_D1, blockIdx.y*32, blockIdx.x*32);
    } else {
        int flat = blockIdx.x + blockIdx.y*32;       // 0..255
        tblock(d2w, w2, 1024, 256, C_D2, (flat/8)*32, (flat%8)*32);
    }
}

// ---------------- load helpers ---------------------------------------------
__device__ __forceinline__ void issue_conv(Tiles* t, int b, int h, int n0,
                                           int kc, int tid){
    int tap = kc >> 3, ci0 = (kc & 7) * 32;
    int dh = tap/3 - 1, dw = tap%3 - 1;
    int hp = h + dh;
    bool hv = (unsigned)hp < 128u;
#pragma unroll
    for (int j = 0; j < 2; j++){
        int lin = tid + j*256;
        int r = lin >> 2, ch = lin & 3;
        int wp = r + dw;
        bool v = hv && ((unsigned)wp < 128u);
        const __half* src = v ? (g_xs + ((size_t)((b*128+hp)*128 + wp))*CI + ci0 + ch*8)
                              : (const __half*)g_xs;
        cp16((uint32_t)__cvta_generic_to_shared(&t->A[r][ch*8]), src, v ? 16 : 0);
        cp16((uint32_t)__cvta_generic_to_shared(&t->Bt[r][ch*8]),
             g_wcT + ((size_t)(tap*256 + n0 + r))*CI + ci0 + ch*8, 16);
    }
}

template<int K>
__device__ __forceinline__ void issue_gemm(Tiles* t, const __half* A, const __half* Bw,
                                           size_t m0, int n0, int kc, int tid){
#pragma unroll
    for (int j = 0; j < 2; j++){
        int lin = tid + j*256;
        int r = lin >> 2, ch = lin & 3;
        cp16((uint32_t)__cvta_generic_to_shared(&t->A[r][ch*8]),
             A + (m0 + r)*(size_t)K + kc*32 + ch*8, 16);
        cp16((uint32_t)__cvta_generic_to_shared(&t->Bt[r][ch*8]),
             Bw + (size_t)(n0 + r)*K + kc*32 + ch*8, 16);
    }
}

// ---------------- conv (implicit GEMM, 3-stage, 1 sync/iter) ---------------
__global__ void __launch_bounds__(256,2) conv_kernel(
    const float* __restrict__ bias, const float* __restrict__ noise,
    const float* __restrict__ ncoef)
{
    extern __shared__ Tiles tiles[];     // 3 stages
    int tid = threadIdx.x;
    int bh = blockIdx.y; int b = bh >> 7, h = bh & 127;
    int n0 = blockIdx.x * 128;
    int wid = tid >> 5, lane = tid & 31;
    int wm = wid >> 1, wn = wid & 1, qr = lane >> 2, qc = lane & 3;

    float acc[2][8][4];
#pragma unroll
    for (int i = 0; i < 2; i++)
#pragma unroll
        for (int j = 0; j < 8; j++)
#pragma unroll
            for (int k = 0; k < 4; k++) acc[i][j][k] = 0.f;

    const int NK = 72;
    issue_conv(&tiles[0], b, h, n0, 0, tid); cp_commit();
    issue_conv(&tiles[1], b, h, n0, 1, tid); cp_commit();
#pragma unroll 1
    for (int s = 0; s < NK; s++){
        cp_wait<1>();
        __syncthreads();
        if (s + 2 < NK) issue_conv(&tiles[(s+2)%3], b, h, n0, s+2, tid);
        cp_commit();
        compute_tile(tiles[s%3], acc, wm, wn, qr, qc);
    }

    size_t prow = (size_t)(b*128 + h) * 128;
#pragma unroll
    for (int mt = 0; mt < 2; mt++){
#pragma unroll
        for (int nt = 0; nt < 8; nt++){
            int col = n0 + wn*64 + nt*8 + 2*qc;
            float d0 = g_d[b*CO+col], d1 = g_d[b*CO+col+1];
            float b0 = bias[col], b1 = bias[col+1];
            float nc0 = ncoef[col], nc1 = ncoef[col+1];
#pragma unroll
            for (int r2 = 0; r2 < 2; r2++){
                int w = wm*32 + mt*16 + qr + r2*8;
                size_t p = prow + w;
                float2 nz = *(const float2*)(noise + p*CO + col);
                float v0 = lrelu(acc[mt][nt][r2*2+0]*d0 + b0 + nz.x*nc0);
                float v1 = lrelu(acc[mt][nt][r2*2+1]*d1 + b1 + nz.y*nc1);
                __half2 hv = __floats2half2_rn(v0, v1);
                *(uint32_t*)(g_y + p*CO + col) = *(uint32_t*)&hv;
            }
        }
    }
}

// ---------------- generic GEMM (3-stage, 1 sync/iter) ----------------------
template<int K, int N, bool HALF_OUT>
__global__ void __launch_bounds__(256,2) gemm_kernel(
    const __half* __restrict__ A, const __half* __restrict__ Bw,
    const float* __restrict__ bias, void* __restrict__ outv)
{
    extern __shared__ Tiles tiles[];
    int tid = threadIdx.x;
    size_t m0 = (size_t)blockIdx.y * 128;
    int n0 = blockIdx.x * 128;
    int wid = tid >> 5, lane = tid & 31;
    int wm = wid >> 1, wn = wid & 1, qr = lane >> 2, qc = lane & 3;

    float acc[2][8][4];
#pragma unroll
    for (int i = 0; i < 2; i++)
#pragma unroll
        for (int j = 0; j < 8; j++)
#pragma unroll
            for (int k = 0; k < 4; k++) acc[i][j][k] = 0.f;

    const int NK = K/32;
    issue_gemm<K>(&tiles[0], A, Bw, m0, n0, 0, tid); cp_commit();
    issue_gemm<K>(&tiles[1], A, Bw, m0, n0, 1, tid); cp_commit();
#pragma unroll 1
    for (int s = 0; s < NK; s++){
        cp_wait<1>();
        __syncthreads();
        if (s + 2 < NK) issue_gemm<K>(&tiles[(s+2)%3], A, Bw, m0, n0, s+2, tid);
        cp_commit();
        compute_tile(tiles[s%3], acc, wm, wn, qr, qc);
    }

#pragma unroll
    for (int mt = 0; mt < 2; mt++){
#pragma unroll
        for (int nt = 0; nt < 8; nt++){
            int col = n0 + wn*64 + nt*8 + 2*qc;
            float b0 = bias[col], b1 = bias[col+1];
#pragma unroll
            for (int r2 = 0; r2 < 2; r2++){
                size_t m = m0 + wm*32 + mt*16 + qr + r2*8;
                float v0 = lrelu(acc[mt][nt][r2*2+0] + b0);
                float v1 = lrelu(acc[mt][nt][r2*2+1] + b1);
                if (HALF_OUT){
                    __half2 hv = __floats2half2_rn(v0, v1);
                    *(uint32_t*)((__half*)outv + m*(size_t)N + col) = *(uint32_t*)&hv;
                } else {
                    *(float2*)((float*)outv + m*(size_t)N + col) = make_float2(v0, v1);
                }
            }
        }
    }
}

// ---------------- launch ----------------------------------------------------
extern "C" void kernel_launch(void* const* d_in, const int* in_sizes, int n_in,
                              void* d_out, int out_size){
    const float* data   = (const float*)d_in[0];
    const float* latent = (const float*)d_in[1];
    const float* noise  = (const float*)d_in[2];
    const float* stdW   = (const float*)d_in[3];
    const float* stdb   = (const float*)d_in[4];
    const float* convw  = (const float*)d_in[5];
    const float* bias   = (const float*)d_in[6];
    const float* ncoef  = (const float*)d_in[7];
    const float* d1w    = (const float*)d_in[8];
    const float* d1b    = (const float*)d_in[9];
    const float* d2w    = (const float*)d_in[10];
    const float* d2b    = (const float*)d_in[11];
    float* out = (float*)d_out;

    void *p_wc, *p_w1, *p_w2, *p_y, *p_h;
    cudaGetSymbolAddress(&p_wc, g_wcT);
    cudaGetSymbolAddress(&p_w1, g_w1T);
    cudaGetSymbolAddress(&p_w2, g_w2T);
    cudaGetSymbolAddress(&p_y,  g_y);
    cudaGetSymbolAddress(&p_h,  g_h);

    int smem = (int)sizeof(Tiles) * 3;   // 61440 B, 3-stage
    cudaFuncSetAttribute(conv_kernel, cudaFuncAttributeMaxDynamicSharedMemorySize, smem);
    cudaFuncSetAttribute(gemm_kernel<256,1024,true>,  cudaFuncAttributeMaxDynamicSharedMemorySize, smem);
    cudaFuncSetAttribute(gemm_kernel<1024,256,false>, cudaFuncAttributeMaxDynamicSharedMemorySize, smem);

    // launch order arranged so ncu (-s 5 -c 1) profiles conv_kernel (6th launch)
    s_kernel<<<NB, CI>>>(latent, stdW, stdb);
    d_kernel<<<NB, CO>>>(convw);
    mod_kernel<<<32768, 256>>>(data);
    tscale_conv<<<dim3(8,8,9),  dim3(32,8)>>>(convw, (__half*)p_wc);
    tscale_d12 <<<dim3(32,8,2), dim3(32,8)>>>(d1w, d2w, (__half*)p_w1, (__half*)p_w2);

    conv_kernel<<<dim3(2,1024), 256, smem>>>(bias, noise, ncoef);
    gemm_kernel<256,1024,true ><<<dim3(8,1024), 256, smem>>>(
        (const __half*)p_y, (const __half*)p_w1, d1b, p_h);
    gemm_kernel<1024,256,false><<<dim3(2,1024), 256, smem>>>(
        (const __half*)p_h, (const __half*)p_w2, d2b, (void*)out);
}

// round 6
// speedup vs baseline: 2.8845x; 1.2696x over previous
#include <cuda_runtime.h>
#include <cuda_fp16.h>
#include <cstdint>
#include <cstddef>

#define NB 8
#define CI 256
#define CO 256
#define NL 512
#define NPIX (8*128*128)

#define C_STD  0.0625f
#define C_CONV 0.02946278254943948f
#define C_D1   0.08838834764831845f
#define C_D2   0.04419417382415922f

// ---------------- scratch --------------------------------------------------
__device__ float  g_s[NB*CI];
__device__ float  g_d[NB*CO];
__device__ __half g_xs[(size_t)NPIX*CI];       // modulated input, fp16
__device__ __half g_wcT[9*CO*CI];              // conv w [tap][co][ci], scaled
__device__ __half g_w1T[4*CO*CO];              // D1 w [n=1024][k=256]
__device__ __half g_w2T[(size_t)CO*4*CO];      // D2 w [n=256][k=1024]
__device__ __half g_y[(size_t)NPIX*CO];        // conv out (post-lrelu)
__device__ __half g_h[(size_t)NPIX*4*CO];      // D1 out (post-lrelu)

// ---------------- helpers --------------------------------------------------
__device__ __forceinline__ float lrelu(float x){ return x > 0.f ? x : 0.2f*x; }

__device__ __forceinline__ void mma16(float c[4], const uint32_t a[4], const uint32_t b[2]){
    asm volatile("mma.sync.aligned.m16n8k16.row.col.f32.f16.f16.f32 "
        "{%0,%1,%2,%3}, {%4,%5,%6,%7}, {%8,%9}, {%0,%1,%2,%3};\n"
        : "+f"(c[0]), "+f"(c[1]), "+f"(c[2]), "+f"(c[3])
        : "r"(a[0]), "r"(a[1]), "r"(a[2]), "r"(a[3]), "r"(b[0]), "r"(b[1]));
}
__device__ __forceinline__ void ldsm4(uint32_t& r0, uint32_t& r1, uint32_t& r2,
                                      uint32_t& r3, uint32_t addr){
    asm volatile("ldmatrix.sync.aligned.m8n8.x4.shared.b16 {%0,%1,%2,%3}, [%4];"
        : "=r"(r0), "=r"(r1), "=r"(r2), "=r"(r3) : "r"(addr));
}
__device__ __forceinline__ void cp16(uint32_t d, const void* s, int nbytes){
    asm volatile("cp.async.ca.shared.global [%0], [%1], 16, %2;\n"
                 :: "r"(d), "l"(s), "r"(nbytes));
}
__device__ __forceinline__ void cp_commit(){ asm volatile("cp.async.commit_group;\n"); }
template<int N> __device__ __forceinline__ void cp_wait(){
    asm volatile("cp.async.wait_group %0;\n" :: "n"(N));
}

// ---------------- tile layout ----------------------------------------------
// K-chunk 64. Row stride 72 halves (144 B): LDSM rows hit rotating 4-bank
// groups (36r mod 32 = 4r) -> conflict-free; 16B-aligned (144 = 9*16).
struct Tiles {
    __half A[128][72];    // [M][K=64]
    __half Bt[128][72];   // [N][K=64] (weights pre-transposed to [N][K])
};

__device__ __forceinline__ void compute_tile(const Tiles& t, float acc[2][8][4],
                                             int wm, int wn, int lane){
    uint32_t aBase = (uint32_t)__cvta_generic_to_shared(&t.A[0][0]);
    uint32_t bBase = (uint32_t)__cvta_generic_to_shared(&t.Bt[0][0]);
    // A: matrices (m-lo/k-lo, m-hi/k-lo, m-lo/k-hi, m-hi/k-hi)
    uint32_t aOff = aBase + (uint32_t)(((wm*32 + (lane & 15))*72 + (lane >> 4)*8)*2);
    // B: lane group g=lane>>3: n-blk (g>>1), k-half (g&1)
    int g = lane >> 3;
    uint32_t bOff = bBase + (uint32_t)(((wn*64 + (g >> 1)*8 + (lane & 7))*72 + (g & 1)*8)*2);
#pragma unroll
    for (int kk = 0; kk < 4; kk++){
        uint32_t a[2][4];
#pragma unroll
        for (int mt = 0; mt < 2; mt++)
            ldsm4(a[mt][0], a[mt][1], a[mt][2], a[mt][3],
                  aOff + kk*32 + mt*(16*72*2));
        uint32_t b[8][2];
#pragma unroll
        for (int nt2 = 0; nt2 < 4; nt2++){
            uint32_t r0, r1, r2, r3;
            ldsm4(r0, r1, r2, r3, bOff + kk*32 + nt2*(16*72*2));
            b[2*nt2][0] = r0; b[2*nt2][1] = r1;
            b[2*nt2+1][0] = r2; b[2*nt2+1][1] = r3;
        }
#pragma unroll
        for (int mt = 0; mt < 2; mt++)
#pragma unroll
            for (int nt = 0; nt < 8; nt++)
                mma16(acc[mt][nt], a[mt], b[nt]);
    }
}

// ---------------- prep kernels ---------------------------------------------
__global__ void s_kernel(const float* __restrict__ latent,
                         const float* __restrict__ stdW,
                         const float* __restrict__ stdb){
    int b = blockIdx.x, i = threadIdx.x;
    float acc = 0.f;
    for (int l = 0; l < NL; l++) acc += latent[b*NL+l] * stdW[l*CI+i];
    g_s[b*CI+i] = acc * C_STD + stdb[i];
}

__global__ void d_kernel(const float* __restrict__ cw){
    int b = blockIdx.x, o = threadIdx.x;
    float acc = 0.f;
    for (int i = 0; i < CI; i++){
        float w2 = 0.f;
#pragma unroll
        for (int k = 0; k < 9; k++){
            float wv = cw[(size_t)(k*CI + i)*CO + o];
            w2 += wv*wv;
        }
        float sv = g_s[b*CI+i];
        acc += w2 * sv * sv;
    }
    g_d[b*CO+o] = rsqrtf(acc * (C_CONV*C_CONV) + 1e-8f);
}

__global__ void mod_kernel(const float* __restrict__ data){
    size_t idx = ((size_t)blockIdx.x * blockDim.x + threadIdx.x) * 4;
    float4 x = *(const float4*)(data + idx);
    int c = (int)(idx & (CI-1));
    int b = (int)(idx >> 22);
    float4 s = *(const float4*)(g_s + b*CI + c);
    __half2 h0 = __floats2half2_rn(x.x*s.x, x.y*s.y);
    __half2 h1 = __floats2half2_rn(x.z*s.z, x.w*s.w);
    uint2 pk; pk.x = *(uint32_t*)&h0; pk.y = *(uint32_t*)&h1;
    *(uint2*)(g_xs + idx) = pk;
}

__device__ __forceinline__ void tblock(const float* src, __half* dst,
                                       int R, int C, float sc, int r0, int c0){
    __shared__ float t[32][33];
    int x = threadIdx.x, y = threadIdx.y;   // 32 x 8
#pragma unroll
    for (int i = 0; i < 32; i += 8)
        t[y+i][x] = src[(size_t)(r0+y+i)*C + c0+x];
    __syncthreads();
#pragma unroll
    for (int i = 0; i < 32; i += 8)
        dst[(size_t)(c0+y+i)*R + r0+x] = __float2half_rn(t[x][y+i]*sc);
}

__global__ void tscale_conv(const float* __restrict__ src, __half* __restrict__ dst){
    size_t off = (size_t)blockIdx.z * 256 * 256;
    tblock(src + off, dst + off, 256, 256, C_CONV, blockIdx.y*32, blockIdx.x*32);
}
__global__ void tscale_d12(const float* __restrict__ d1w, const float* __restrict__ d2w,
                           __half* __restrict__ w1, __half* __restrict__ w2){
    if (blockIdx.z == 0){
        tblock(d1w, w1, 256, 1024, C_D1, blockIdx.y*32, blockIdx.x*32);
    } else {
        int flat = blockIdx.x + blockIdx.y*32;
        tblock(d2w, w2, 1024, 256, C_D2, (flat/8)*32, (flat%8)*32);
    }
}

// ---------------- load helpers (K-chunk 64: 4 cp16/thread per tile pair) ---
__device__ __forceinline__ void issue_conv(Tiles* t, int b, int h, int n0,
                                           int s, int tid){
    int tap = s >> 2, ci0 = (s & 3) * 64;
    int dh = tap/3 - 1, dw = tap%3 - 1;
    int hp = h + dh;
    bool hv = (unsigned)hp < 128u;
#pragma unroll
    for (int j = 0; j < 4; j++){
        int lin = tid + j*256;
        int r = lin >> 3, c8 = (lin & 7) * 8;
        int wp = r + dw;
        bool v = hv && ((unsigned)wp < 128u);
        const __half* src = v ? (g_xs + ((size_t)((b*128+hp)*128 + wp))*CI + ci0 + c8)
                              : (const __half*)g_xs;
        cp16((uint32_t)__cvta_generic_to_shared(&t->A[r][c8]), src, v ? 16 : 0);
        cp16((uint32_t)__cvta_generic_to_shared(&t->Bt[r][c8]),
             g_wcT + ((size_t)(tap*256 + n0 + r))*CI + ci0 + c8, 16);
    }
}

template<int K>
__device__ __forceinline__ void issue_gemm(Tiles* t, const __half* A, const __half* Bw,
                                           size_t m0, int n0, int s, int tid){
#pragma unroll
    for (int j = 0; j < 4; j++){
        int lin = tid + j*256;
        int r = lin >> 3, c8 = (lin & 7) * 8;
        cp16((uint32_t)__cvta_generic_to_shared(&t->A[r][c8]),
             A + (m0 + r)*(size_t)K + s*64 + c8, 16);
        cp16((uint32_t)__cvta_generic_to_shared(&t->Bt[r][c8]),
             Bw + (size_t)(n0 + r)*K + s*64 + c8, 16);
    }
}

// ---------------- conv (implicit GEMM, K64, 2-stage) ------------------------
__global__ void __launch_bounds__(256,2) conv_kernel(
    const float* __restrict__ bias, const float* __restrict__ noise,
    const float* __restrict__ ncoef)
{
    extern __shared__ Tiles tiles[];     // 2 stages
    int tid = threadIdx.x;
    int bh = blockIdx.y; int b = bh >> 7, h = bh & 127;
    int n0 = blockIdx.x * 128;
    int wid = tid >> 5, lane = tid & 31;
    int wm = wid >> 1, wn = wid & 1, qr = lane >> 2, qc = lane & 3;

    float acc[2][8][4];
#pragma unroll
    for (int i = 0; i < 2; i++)
#pragma unroll
        for (int j = 0; j < 8; j++)
#pragma unroll
            for (int k = 0; k < 4; k++) acc[i][j][k] = 0.f;

    const int NK = 36;
    issue_conv(&tiles[0], b, h, n0, 0, tid); cp_commit();
#pragma unroll 1
    for (int s = 0; s < NK; s++){
        cp_wait<0>();
        __syncthreads();
        if (s + 1 < NK){ issue_conv(&tiles[(s+1)&1], b, h, n0, s+1, tid); cp_commit(); }
        compute_tile(tiles[s&1], acc, wm, wn, lane);
    }

    size_t prow = (size_t)(b*128 + h) * 128;
#pragma unroll
    for (int mt = 0; mt < 2; mt++){
#pragma unroll
        for (int nt = 0; nt < 8; nt++){
            int col = n0 + wn*64 + nt*8 + 2*qc;
            float d0 = g_d[b*CO+col], d1 = g_d[b*CO+col+1];
            float b0 = bias[col], b1 = bias[col+1];
            float nc0 = ncoef[col], nc1 = ncoef[col+1];
#pragma unroll
            for (int r2 = 0; r2 < 2; r2++){
                int w = wm*32 + mt*16 + qr + r2*8;
                size_t p = prow + w;
                float2 nz = *(const float2*)(noise + p*CO + col);
                float v0 = lrelu(acc[mt][nt][r2*2+0]*d0 + b0 + nz.x*nc0);
                float v1 = lrelu(acc[mt][nt][r2*2+1]*d1 + b1 + nz.y*nc1);
                __half2 hv = __floats2half2_rn(v0, v1);
                *(uint32_t*)(g_y + p*CO + col) = *(uint32_t*)&hv;
            }
        }
    }
}

// ---------------- generic GEMM (K64, 2-stage) -------------------------------
template<int K, int N, bool HALF_OUT>
__global__ void __launch_bounds__(256,2) gemm_kernel(
    const __half* __restrict__ A, const __half* __restrict__ Bw,
    const float* __restrict__ bias, void* __restrict__ outv)
{
    extern __shared__ Tiles tiles[];
    int tid = threadIdx.x;
    size_t m0 = (size_t)blockIdx.y * 128;
    int n0 = blockIdx.x * 128;
    int wid = tid >> 5, lane = tid & 31;
    int wm = wid >> 1, wn = wid & 1, qr = lane >> 2, qc = lane & 3;

    float acc[2][8][4];
#pragma unroll
    for (int i = 0; i < 2; i++)
#pragma unroll
        for (int j = 0; j < 8; j++)
#pragma unroll
            for (int k = 0; k < 4; k++) acc[i][j][k] = 0.f;

    const int NK = K/64;
    issue_gemm<K>(&tiles[0], A, Bw, m0, n0, 0, tid); cp_commit();
#pragma unroll 1
    for (int s = 0; s < NK; s++){
        cp_wait<0>();
        __syncthreads();
        if (s + 1 < NK){ issue_gemm<K>(&tiles[(s+1)&1], A, Bw, m0, n0, s+1, tid); cp_commit(); }
        compute_tile(tiles[s&1], acc, wm, wn, lane);
    }

#pragma unroll
    for (int mt = 0; mt < 2; mt++){
#pragma unroll
        for (int nt = 0; nt < 8; nt++){
            int col = n0 + wn*64 + nt*8 + 2*qc;
            float b0 = bias[col], b1 = bias[col+1];
#pragma unroll
            for (int r2 = 0; r2 < 2; r2++){
                size_t m = m0 + wm*32 + mt*16 + qr + r2*8;
                float v0 = lrelu(acc[mt][nt][r2*2+0] + b0);
                float v1 = lrelu(acc[mt][nt][r2*2+1] + b1);
                if (HALF_OUT){
                    __half2 hv = __floats2half2_rn(v0, v1);
                    *(uint32_t*)((__half*)outv + m*(size_t)N + col) = *(uint32_t*)&hv;
                } else {
                    *(float2*)((float*)outv + m*(size_t)N + col) = make_float2(v0, v1);
                }
            }
        }
    }
}

// ---------------- launch ----------------------------------------------------
extern "C" void kernel_launch(void* const* d_in, const int* in_sizes, int n_in,
                              void* d_out, int out_size){
    const float* data   = (const float*)d_in[0];
    const float* latent = (const float*)d_in[1];
    const float* noise  = (const float*)d_in[2];
    const float* stdW   = (const float*)d_in[3];
    const float* stdb   = (const float*)d_in[4];
    const float* convw  = (const float*)d_in[5];
    const float* bias   = (const float*)d_in[6];
    const float* ncoef  = (const float*)d_in[7];
    const float* d1w    = (const float*)d_in[8];
    const float* d1b    = (const float*)d_in[9];
    const float* d2w    = (const float*)d_in[10];
    const float* d2b    = (const float*)d_in[11];
    float* out = (float*)d_out;

    void *p_wc, *p_w1, *p_w2, *p_y, *p_h;
    cudaGetSymbolAddress(&p_wc, g_wcT);
    cudaGetSymbolAddress(&p_w1, g_w1T);
    cudaGetSymbolAddress(&p_w2, g_w2T);
    cudaGetSymbolAddress(&p_y,  g_y);
    cudaGetSymbolAddress(&p_h,  g_h);

    int smem = (int)sizeof(Tiles) * 2;   // 73728 B, 2-stage K64
    cudaFuncSetAttribute(conv_kernel, cudaFuncAttributeMaxDynamicSharedMemorySize, smem);
    cudaFuncSetAttribute(gemm_kernel<256,1024,true>,  cudaFuncAttributeMaxDynamicSharedMemorySize, smem);
    cudaFuncSetAttribute(gemm_kernel<1024,256,false>, cudaFuncAttributeMaxDynamicSharedMemorySize, smem);

    // order keeps conv_kernel as the 6th launch for ncu -s 5 -c 1
    s_kernel<<<NB, CI>>>(latent, stdW, stdb);
    d_kernel<<<NB, CO>>>(convw);
    mod_kernel<<<32768, 256>>>(data);
    tscale_conv<<<dim3(8,8,9),  dim3(32,8)>>>(convw, (__half*)p_wc);
    tscale_d12 <<<dim3(32,8,2), dim3(32,8)>>>(d1w, d2w, (__half*)p_w1, (__half*)p_w2);

    conv_kernel<<<dim3(2,1024), 256, smem>>>(bias, noise, ncoef);
    gemm_kernel<256,1024,true ><<<dim3(8,1024), 256, smem>>>(
        (const __half*)p_y, (const __half*)p_w1, d1b, p_h);
    gemm_kernel<1024,256,false><<<dim3(2,1024), 256, smem>>>(
        (const __half*)p_h, (const __half*)p_w2, d2b, (void*)out);
}

// round 7
// speedup vs baseline: 3.0720x; 1.0650x over previous
#include <cuda_runtime.h>
#include <cuda_fp16.h>
#include <cstdint>
#include <cstddef>

#define NB 8
#define CI 256
#define CO 256
#define NL 512
#define NPIX (8*128*128)
#define NTILES 32768            // 8 * 64 * 64 winograd tiles

#define C_STD  0.0625f
#define C_CONV 0.02946278254943948f
#define C_D1   0.08838834764831845f
#define C_D2   0.04419417382415922f

// ---------------- scratch --------------------------------------------------
__device__ float  g_s[NB*CI];
__device__ float  g_d[NB*CO];
__device__ __half g_xs[(size_t)NPIX*CI];        // modulated input, fp16
__device__ __half g_U[(size_t)16*CO*CI];        // winograd weights [p][co][ci]
__device__ __half g_V[(size_t)16*NTILES*CI];    // winograd input  [p][tile][ci]
__device__ __half g_w1T[4*CO*CO];               // D1 w [n=1024][k=256]
__device__ __half g_w2T[(size_t)CO*4*CO];       // D2 w [n=256][k=1024]
__device__ __half g_y[(size_t)NPIX*CO];         // conv out (post-lrelu)
__device__ __half g_h[(size_t)NPIX*4*CO];       // D1 out; ALSO aliased as M [p][tile][co]

// ---------------- helpers --------------------------------------------------
__device__ __forceinline__ float lrelu(float x){ return x > 0.f ? x : 0.2f*x; }

__device__ __forceinline__ void mma16(float c[4], const uint32_t a[4], const uint32_t b[2]){
    asm volatile("mma.sync.aligned.m16n8k16.row.col.f32.f16.f16.f32 "
        "{%0,%1,%2,%3}, {%4,%5,%6,%7}, {%8,%9}, {%0,%1,%2,%3};\n"
        : "+f"(c[0]), "+f"(c[1]), "+f"(c[2]), "+f"(c[3])
        : "r"(a[0]), "r"(a[1]), "r"(a[2]), "r"(a[3]), "r"(b[0]), "r"(b[1]));
}
__device__ __forceinline__ void ldsm4(uint32_t& r0, uint32_t& r1, uint32_t& r2,
                                      uint32_t& r3, uint32_t addr){
    asm volatile("ldmatrix.sync.aligned.m8n8.x4.shared.b16 {%0,%1,%2,%3}, [%4];"
        : "=r"(r0), "=r"(r1), "=r"(r2), "=r"(r3) : "r"(addr));
}
__device__ __forceinline__ void cp16(uint32_t d, const void* s, int nbytes){
    asm volatile("cp.async.ca.shared.global [%0], [%1], 16, %2;\n"
                 :: "r"(d), "l"(s), "r"(nbytes));
}
__device__ __forceinline__ void cp_commit(){ asm volatile("cp.async.commit_group;\n"); }
template<int N> __device__ __forceinline__ void cp_wait(){
    asm volatile("cp.async.wait_group %0;\n" :: "n"(N));
}

// ---------------- tile layout (unchanged from R6) ---------------------------
struct Tiles {
    __half A[128][72];
    __half Bt[128][72];
};

__device__ __forceinline__ void compute_tile(const Tiles& t, float acc[2][8][4],
                                             int wm, int wn, int lane){
    uint32_t aBase = (uint32_t)__cvta_generic_to_shared(&t.A[0][0]);
    uint32_t bBase = (uint32_t)__cvta_generic_to_shared(&t.Bt[0][0]);
    uint32_t aOff = aBase + (uint32_t)(((wm*32 + (lane & 15))*72 + (lane >> 4)*8)*2);
    int g = lane >> 3;
    uint32_t bOff = bBase + (uint32_t)(((wn*64 + (g >> 1)*8 + (lane & 7))*72 + (g & 1)*8)*2);
#pragma unroll
    for (int kk = 0; kk < 4; kk++){
        uint32_t a[2][4];
#pragma unroll
        for (int mt = 0; mt < 2; mt++)
            ldsm4(a[mt][0], a[mt][1], a[mt][2], a[mt][3],
                  aOff + kk*32 + mt*(16*72*2));
        uint32_t b[8][2];
#pragma unroll
        for (int nt2 = 0; nt2 < 4; nt2++){
            uint32_t r0, r1, r2, r3;
            ldsm4(r0, r1, r2, r3, bOff + kk*32 + nt2*(16*72*2));
            b[2*nt2][0] = r0; b[2*nt2][1] = r1;
            b[2*nt2+1][0] = r2; b[2*nt2+1][1] = r3;
        }
#pragma unroll
        for (int mt = 0; mt < 2; mt++)
#pragma unroll
            for (int nt = 0; nt < 8; nt++)
                mma16(acc[mt][nt], a[mt], b[nt]);
    }
}

// ---------------- prep kernels ---------------------------------------------
__global__ void s_kernel(const float* __restrict__ latent,
                         const float* __restrict__ stdW,
                         const float* __restrict__ stdb){
    int b = blockIdx.x, i = threadIdx.x;
    float acc = 0.f;
    for (int l = 0; l < NL; l++) acc += latent[b*NL+l] * stdW[l*CI+i];
    g_s[b*CI+i] = acc * C_STD + stdb[i];
}

__global__ void d_kernel(const float* __restrict__ cw){
    int b = blockIdx.x, o = threadIdx.x;
    float acc = 0.f;
    for (int i = 0; i < CI; i++){
        float w2 = 0.f;
#pragma unroll
        for (int k = 0; k < 9; k++){
            float wv = cw[(size_t)(k*CI + i)*CO + o];
            w2 += wv*wv;
        }
        float sv = g_s[b*CI+i];
        acc += w2 * sv * sv;
    }
    g_d[b*CO+o] = rsqrtf(acc * (C_CONV*C_CONV) + 1e-8f);
}

__global__ void mod_kernel(const float* __restrict__ data){
    size_t idx = ((size_t)blockIdx.x * blockDim.x + threadIdx.x) * 4;
    float4 x = *(const float4*)(data + idx);
    int c = (int)(idx & (CI-1));
    int b = (int)(idx >> 22);
    float4 s = *(const float4*)(g_s + b*CI + c);
    __half2 h0 = __floats2half2_rn(x.x*s.x, x.y*s.y);
    __half2 h1 = __floats2half2_rn(x.z*s.z, x.w*s.w);
    uint2 pk; pk.x = *(uint32_t*)&h0; pk.y = *(uint32_t*)&h1;
    *(uint2*)(g_xs + idx) = pk;
}

__device__ __forceinline__ void tblock(const float* src, __half* dst,
                                       int R, int C, float sc, int r0, int c0){
    __shared__ float t[32][33];
    int x = threadIdx.x, y = threadIdx.y;   // 32 x 8
#pragma unroll
    for (int i = 0; i < 32; i += 8)
        t[y+i][x] = src[(size_t)(r0+y+i)*C + c0+x];
    __syncthreads();
#pragma unroll
    for (int i = 0; i < 32; i += 8)
        dst[(size_t)(c0+y+i)*R + r0+x] = __float2half_rn(t[x][y+i]*sc);
}
__global__ void tscale_d12(const float* __restrict__ d1w, const float* __restrict__ d2w,
                           __half* __restrict__ w1, __half* __restrict__ w2){
    if (blockIdx.z == 0){
        tblock(d1w, w1, 256, 1024, C_D1, blockIdx.y*32, blockIdx.x*32);
    } else {
        int flat = blockIdx.x + blockIdx.y*32;
        tblock(d2w, w2, 1024, 256, C_D2, (flat/8)*32, (flat%8)*32);
    }
}

// ---------------- winograd weight transform: U = G g G^T --------------------
// grid (8 ci-blocks, 8 co-blocks), block (32,8)
__global__ void wtrans(const float* __restrict__ cw){
    __shared__ float sg[9][32][33];      // [tap][ci][co]
    int ci0 = blockIdx.x*32, co0 = blockIdx.y*32;
    int x = threadIdx.x, y = threadIdx.y;
    int tid = y*32 + x;
#pragma unroll
    for (int k = 0; k < 9; k++)
#pragma unroll
        for (int i = 0; i < 32; i += 8)
            sg[k][y+i][x] = cw[((size_t)(k*256 + ci0 + y + i))*256 + co0 + x];
    __syncthreads();
#pragma unroll
    for (int j = 0; j < 4; j++){
        int pair = tid + j*256;
        int ci = pair & 31, co = pair >> 5;
        float g[3][3];
#pragma unroll
        for (int r = 0; r < 3; r++)
#pragma unroll
            for (int c = 0; c < 3; c++)
                g[r][c] = sg[r*3+c][ci][co] * C_CONV;
        float t[4][3];
#pragma unroll
        for (int c = 0; c < 3; c++){
            t[0][c] = g[0][c];
            t[1][c] = 0.5f*(g[0][c] + g[1][c] + g[2][c]);
            t[2][c] = 0.5f*(g[0][c] - g[1][c] + g[2][c]);
            t[3][c] = g[2][c];
        }
#pragma unroll
        for (int r = 0; r < 4; r++){
            float u0 = t[r][0];
            float u1 = 0.5f*(t[r][0] + t[r][1] + t[r][2]);
            float u2 = 0.5f*(t[r][0] - t[r][1] + t[r][2]);
            float u3 = t[r][2];
            int p = r*4;
            g_U[((size_t)(p+0)*256 + co0+co)*256 + ci0+ci] = __float2half_rn(u0);
            g_U[((size_t)(p+1)*256 + co0+co)*256 + ci0+ci] = __float2half_rn(u1);
            g_U[((size_t)(p+2)*256 + co0+co)*256 + ci0+ci] = __float2half_rn(u2);
            g_U[((size_t)(p+3)*256 + co0+co)*256 + ci0+ci] = __float2half_rn(u3);
        }
    }
}

// ---------------- winograd input transform: V = B^T d B ---------------------
// grid (64, 512): x = tx, y = b*64+ty; 256 threads = ci
__global__ void vtrans(){
    int ci = threadIdx.x;
    int tx = blockIdx.x;
    int b = blockIdx.y >> 6, ty = blockIdx.y & 63;
    size_t t = (size_t)blockIdx.y*64 + tx;
    int ir0 = 2*ty - 1, ic0 = 2*tx - 1;
    float d[4][4];
#pragma unroll
    for (int r = 0; r < 4; r++){
        int ir = ir0 + r;
        bool rv = (unsigned)ir < 128u;
#pragma unroll
        for (int c = 0; c < 4; c++){
            int ic = ic0 + c;
            bool v = rv && ((unsigned)ic < 128u);
            d[r][c] = v ? __half2float(g_xs[((size_t)((b*128+ir)*128 + ic))*256 + ci]) : 0.f;
        }
    }
    float w[4][4];
#pragma unroll
    for (int c = 0; c < 4; c++){
        w[0][c] = d[0][c] - d[2][c];
        w[1][c] = d[1][c] + d[2][c];
        w[2][c] = d[2][c] - d[1][c];
        w[3][c] = d[1][c] - d[3][c];
    }
#pragma unroll
    for (int r = 0; r < 4; r++){
        float v0 = w[r][0] - w[r][2];
        float v1 = w[r][1] + w[r][2];
        float v2 = w[r][2] - w[r][1];
        float v3 = w[r][1] - w[r][3];
        int p = r*4;
        g_V[((size_t)(p+0)*NTILES + t)*256 + ci] = __float2half_rn(v0);
        g_V[((size_t)(p+1)*NTILES + t)*256 + ci] = __float2half_rn(v1);
        g_V[((size_t)(p+2)*NTILES + t)*256 + ci] = __float2half_rn(v2);
        g_V[((size_t)(p+3)*NTILES + t)*256 + ci] = __float2half_rn(v3);
    }
}

// ---------------- winograd output transform + epilogue ----------------------
// grid (64, 512); 256 threads = co. M aliased in g_h.
__global__ void otrans(const float* __restrict__ bias, const float* __restrict__ noise,
                       const float* __restrict__ ncoef){
    int co = threadIdx.x;
    int tx = blockIdx.x;
    int b = blockIdx.y >> 6, ty = blockIdx.y & 63;
    size_t t = (size_t)blockIdx.y*64 + tx;
    float m[4][4];
#pragma unroll
    for (int p = 0; p < 16; p++)
        m[p>>2][p&3] = __half2float(g_h[((size_t)p*NTILES + t)*256 + co]);
    float z[2][4];
#pragma unroll
    for (int c = 0; c < 4; c++){
        z[0][c] = m[0][c] + m[1][c] + m[2][c];
        z[1][c] = m[1][c] - m[2][c] - m[3][c];
    }
    float dv = g_d[b*256 + co];
    float bv = bias[co], cv = ncoef[co];
#pragma unroll
    for (int r = 0; r < 2; r++){
        float y0 = z[r][0] + z[r][1] + z[r][2];
        float y1 = z[r][1] - z[r][2] - z[r][3];
        int row = 2*ty + r;
#pragma unroll
        for (int c = 0; c < 2; c++){
            float yv = (c == 0) ? y0 : y1;
            int col = 2*tx + c;
            size_t pix = (size_t)(b*128 + row)*128 + col;
            float nz = noise[pix*256 + co];
            float o = lrelu(yv*dv + bv + nz*cv);
            g_y[pix*256 + co] = __float2half_rn(o);
        }
    }
}

// ---------------- generic GEMM (K64, 2-stage; EPI 0=raw half, 1=D1, 2=D2) --
template<int K>
__device__ __forceinline__ void issue_gemm(Tiles* t, const __half* A, const __half* Bw,
                                           size_t m0, int n0, int s, int tid){
#pragma unroll
    for (int j = 0; j < 4; j++){
        int lin = tid + j*256;
        int r = lin >> 3, c8 = (lin & 7) * 8;
        cp16((uint32_t)__cvta_generic_to_shared(&t->A[r][c8]),
             A + (m0 + r)*(size_t)K + s*64 + c8, 16);
        cp16((uint32_t)__cvta_generic_to_shared(&t->Bt[r][c8]),
             Bw + (size_t)(n0 + r)*K + s*64 + c8, 16);
    }
}

template<int K, int N, int EPI>
__global__ void __launch_bounds__(256,2) gemm_kernel(
    const __half* __restrict__ A, const __half* __restrict__ Bw,
    const float* __restrict__ bias, void* __restrict__ outv)
{
    extern __shared__ Tiles tiles[];
    int tid = threadIdx.x;
    size_t m0 = (size_t)blockIdx.y * 128;
    int n0 = blockIdx.x * 128;
    if (EPI == 0){
        size_t z = blockIdx.z;
        A  += z * ((size_t)NTILES*256);
        Bw += z * (256*256);
        outv = (void*)((__half*)outv + z * ((size_t)NTILES*256));
    }
    int wid = tid >> 5, lane = tid & 31;
    int wm = wid >> 1, wn = wid & 1, qr = lane >> 2, qc = lane & 3;

    float acc[2][8][4];
#pragma unroll
    for (int i = 0; i < 2; i++)
#pragma unroll
        for (int j = 0; j < 8; j++)
#pragma unroll
            for (int k = 0; k < 4; k++) acc[i][j][k] = 0.f;

    const int NK = K/64;
    issue_gemm<K>(&tiles[0], A, Bw, m0, n0, 0, tid); cp_commit();
#pragma unroll 1
    for (int s = 0; s < NK; s++){
        cp_wait<0>();
        __syncthreads();
        if (s + 1 < NK){ issue_gemm<K>(&tiles[(s+1)&1], A, Bw, m0, n0, s+1, tid); cp_commit(); }
        compute_tile(tiles[s&1], acc, wm, wn, lane);
    }

#pragma unroll
    for (int mt = 0; mt < 2; mt++){
#pragma unroll
        for (int nt = 0; nt < 8; nt++){
            int col = n0 + wn*64 + nt*8 + 2*qc;
            float b0 = (EPI != 0) ? bias[col]   : 0.f;
            float b1 = (EPI != 0) ? bias[col+1] : 0.f;
#pragma unroll
            for (int r2 = 0; r2 < 2; r2++){
                size_t m = m0 + wm*32 + mt*16 + qr + r2*8;
                float v0 = acc[mt][nt][r2*2+0];
                float v1 = acc[mt][nt][r2*2+1];
                if (EPI != 0){ v0 = lrelu(v0 + b0); v1 = lrelu(v1 + b1); }
                if (EPI == 2){
                    *(float2*)((float*)outv + m*(size_t)N + col) = make_float2(v0, v1);
                } else {
                    __half2 hv = __floats2half2_rn(v0, v1);
                    *(uint32_t*)((__half*)outv + m*(size_t)N + col) = *(uint32_t*)&hv;
                }
            }
        }
    }
}

// ---------------- launch ----------------------------------------------------
extern "C" void kernel_launch(void* const* d_in, const int* in_sizes, int n_in,
                              void* d_out, int out_size){
    const float* data   = (const float*)d_in[0];
    const float* latent = (const float*)d_in[1];
    const float* noise  = (const float*)d_in[2];
    const float* stdW   = (const float*)d_in[3];
    const float* stdb   = (const float*)d_in[4];
    const float* convw  = (const float*)d_in[5];
    const float* bias   = (const float*)d_in[6];
    const float* ncoef  = (const float*)d_in[7];
    const float* d1w    = (const float*)d_in[8];
    const float* d1b    = (const float*)d_in[9];
    const float* d2w    = (const float*)d_in[10];
    const float* d2b    = (const float*)d_in[11];
    float* out = (float*)d_out;

    void *p_U, *p_V, *p_w1, *p_w2, *p_y, *p_h;
    cudaGetSymbolAddress(&p_U,  g_U);
    cudaGetSymbolAddress(&p_V,  g_V);
    cudaGetSymbolAddress(&p_w1, g_w1T);
    cudaGetSymbolAddress(&p_w2, g_w2T);
    cudaGetSymbolAddress(&p_y,  g_y);
    cudaGetSymbolAddress(&p_h,  g_h);

    int smem = (int)sizeof(Tiles) * 2;   // 73728 B
    cudaFuncSetAttribute(gemm_kernel<256,256,0>,  cudaFuncAttributeMaxDynamicSharedMemorySize, smem);
    cudaFuncSetAttribute(gemm_kernel<256,1024,1>, cudaFuncAttributeMaxDynamicSharedMemorySize, smem);
    cudaFuncSetAttribute(gemm_kernel<1024,256,2>, cudaFuncAttributeMaxDynamicSharedMemorySize, smem);

    // ncu -s 5 -c 1 profiles the 6th launch = batched winograd GEMM
    s_kernel<<<NB, CI>>>(latent, stdW, stdb);
    d_kernel<<<NB, CO>>>(convw);
    mod_kernel<<<32768, 256>>>(data);
    wtrans<<<dim3(8,8), dim3(32,8)>>>(convw);
    vtrans<<<dim3(64,512), 256>>>();
    gemm_kernel<256,256,0><<<dim3(2,256,16), 256, smem>>>(
        (const __half*)p_V, (const __half*)p_U, nullptr, p_h);
    tscale_d12<<<dim3(32,8,2), dim3(32,8)>>>(d1w, d2w, (__half*)p_w1, (__half*)p_w2);
    otrans<<<dim3(64,512), 256>>>(bias, noise, ncoef);
    gemm_kernel<256,1024,1><<<dim3(8,1024), 256, smem>>>(
        (const __half*)p_y, (const __half*)p_w1, d1b, p_h);
    gemm_kernel<1024,256,2><<<dim3(2,1024), 256, smem>>>(
        (const __half*)p_h, (const __half*)p_w2, d2b, (void*)out);
}

// round 8
// speedup vs baseline: 3.2593x; 1.0610x over previous
#include <cuda_runtime.h>
#include <cuda_fp16.h>
#include <cstdint>
#include <cstddef>

#define NB 8
#define CI 256
#define CO 256
#define NL 512
#define NPIX (8*128*128)
#define NTILES 32768            // 8 * 64 * 64 winograd tiles

#define C_STD  0.0625f
#define C_CONV 0.02946278254943948f
#define C_D1   0.08838834764831845f
#define C_D2   0.04419417382415922f

// ---------------- scratch --------------------------------------------------
__device__ float  g_s[NB*CI];
__device__ float  g_d[NB*CO];
__device__ int    g_nflag;
__device__ __half g_U[(size_t)16*CO*CI];        // winograd weights [p][co][ci]
__device__ __half g_V[(size_t)16*NTILES*CI];    // winograd input  [p][tile][ci]
__device__ __half g_w1T[4*CO*CO];               // D1 w [n=1024][k=256]
__device__ __half g_w2T[(size_t)CO*4*CO];       // D2 w [n=256][k=1024]
__device__ __half g_y[(size_t)NPIX*CO];         // conv out (post-lrelu)
__device__ __half g_h[(size_t)NPIX*4*CO];       // D1 out; ALSO aliased as M [p][tile][co]

// ---------------- helpers --------------------------------------------------
__device__ __forceinline__ float lrelu(float x){ return x > 0.f ? x : 0.2f*x; }

__device__ __forceinline__ void mma16(float c[4], const uint32_t a[4], const uint32_t b[2]){
    asm volatile("mma.sync.aligned.m16n8k16.row.col.f32.f16.f16.f32 "
        "{%0,%1,%2,%3}, {%4,%5,%6,%7}, {%8,%9}, {%0,%1,%2,%3};\n"
        : "+f"(c[0]), "+f"(c[1]), "+f"(c[2]), "+f"(c[3])
        : "r"(a[0]), "r"(a[1]), "r"(a[2]), "r"(a[3]), "r"(b[0]), "r"(b[1]));
}
__device__ __forceinline__ void ldsm4(uint32_t& r0, uint32_t& r1, uint32_t& r2,
                                      uint32_t& r3, uint32_t addr){
    asm volatile("ldmatrix.sync.aligned.m8n8.x4.shared.b16 {%0,%1,%2,%3}, [%4];"
        : "=r"(r0), "=r"(r1), "=r"(r2), "=r"(r3) : "r"(addr));
}
__device__ __forceinline__ void cp16(uint32_t d, const void* s, int nbytes){
    asm volatile("cp.async.ca.shared.global [%0], [%1], 16, %2;\n"
                 :: "r"(d), "l"(s), "r"(nbytes));
}
__device__ __forceinline__ void cp_commit(){ asm volatile("cp.async.commit_group;\n"); }
template<int N> __device__ __forceinline__ void cp_wait(){
    asm volatile("cp.async.wait_group %0;\n" :: "n"(N));
}

// ---------------- tile layout ----------------------------------------------
struct Tiles {
    __half A[128][72];
    __half Bt[128][72];
};

__device__ __forceinline__ void compute_tile(const Tiles& t, float acc[2][8][4],
                                             int wm, int wn, int lane){
    uint32_t aBase = (uint32_t)__cvta_generic_to_shared(&t.A[0][0]);
    uint32_t bBase = (uint32_t)__cvta_generic_to_shared(&t.Bt[0][0]);
    uint32_t aOff = aBase + (uint32_t)(((wm*32 + (lane & 15))*72 + (lane >> 4)*8)*2);
    int g = lane >> 3;
    uint32_t bOff = bBase + (uint32_t)(((wn*64 + (g >> 1)*8 + (lane & 7))*72 + (g & 1)*8)*2);
#pragma unroll
    for (int kk = 0; kk < 4; kk++){
        uint32_t a[2][4];
#pragma unroll
        for (int mt = 0; mt < 2; mt++)
            ldsm4(a[mt][0], a[mt][1], a[mt][2], a[mt][3],
                  aOff + kk*32 + mt*(16*72*2));
        uint32_t b[8][2];
#pragma unroll
        for (int nt2 = 0; nt2 < 4; nt2++){
            uint32_t r0, r1, r2, r3;
            ldsm4(r0, r1, r2, r3, bOff + kk*32 + nt2*(16*72*2));
            b[2*nt2][0] = r0; b[2*nt2][1] = r1;
            b[2*nt2+1][0] = r2; b[2*nt2+1][1] = r3;
        }
#pragma unroll
        for (int mt = 0; mt < 2; mt++)
#pragma unroll
            for (int nt = 0; nt < 8; nt++)
                mma16(acc[mt][nt], a[mt], b[nt]);
    }
}

// ---------------- prep kernels ---------------------------------------------
__global__ void s_kernel(const float* __restrict__ latent,
                         const float* __restrict__ stdW,
                         const float* __restrict__ stdb){
    if (blockIdx.x == 0 && threadIdx.x == 0) g_nflag = 0;
    int b = blockIdx.x, i = threadIdx.x;
    float acc = 0.f;
    for (int l = 0; l < NL; l++) acc += latent[b*NL+l] * stdW[l*CI+i];
    g_s[b*CI+i] = acc * C_STD + stdb[i];
}

__global__ void d_kernel(const float* __restrict__ cw, const float* __restrict__ ncoef){
    int b = blockIdx.x, o = threadIdx.x;
    if (b == 0 && ncoef[o] != 0.f) atomicOr(&g_nflag, 1);
    float acc = 0.f;
    for (int i = 0; i < CI; i++){
        float w2 = 0.f;
#pragma unroll
        for (int k = 0; k < 9; k++){
            float wv = cw[(size_t)(k*CI + i)*CO + o];
            w2 += wv*wv;
        }
        float sv = g_s[b*CI+i];
        acc += w2 * sv * sv;
    }
    g_d[b*CO+o] = rsqrtf(acc * (C_CONV*C_CONV) + 1e-8f);
}

__device__ __forceinline__ void tblock(const float* src, __half* dst,
                                       int R, int C, float sc, int r0, int c0){
    __shared__ float t[32][33];
    int x = threadIdx.x, y = threadIdx.y;   // 32 x 8
#pragma unroll
    for (int i = 0; i < 32; i += 8)
        t[y+i][x] = src[(size_t)(r0+y+i)*C + c0+x];
    __syncthreads();
#pragma unroll
    for (int i = 0; i < 32; i += 8)
        dst[(size_t)(c0+y+i)*R + r0+x] = __float2half_rn(t[x][y+i]*sc);
}
__global__ void tscale_d12(const float* __restrict__ d1w, const float* __restrict__ d2w,
                           __half* __restrict__ w1, __half* __restrict__ w2){
    if (blockIdx.z == 0){
        tblock(d1w, w1, 256, 1024, C_D1, blockIdx.y*32, blockIdx.x*32);
    } else {
        int flat = blockIdx.x + blockIdx.y*32;
        tblock(d2w, w2, 1024, 256, C_D2, (flat/8)*32, (flat%8)*32);
    }
}

// ---------------- winograd weight transform: U = G g G^T --------------------
__global__ void wtrans(const float* __restrict__ cw){
    __shared__ float sg[9][32][33];      // [tap][ci][co]
    int ci0 = blockIdx.x*32, co0 = blockIdx.y*32;
    int x = threadIdx.x, y = threadIdx.y;
    int tid = y*32 + x;
#pragma unroll
    for (int k = 0; k < 9; k++)
#pragma unroll
        for (int i = 0; i < 32; i += 8)
            sg[k][y+i][x] = cw[((size_t)(k*256 + ci0 + y + i))*256 + co0 + x];
    __syncthreads();
#pragma unroll
    for (int j = 0; j < 4; j++){
        int pair = tid + j*256;
        int ci = pair & 31, co = pair >> 5;
        float g[3][3];
#pragma unroll
        for (int r = 0; r < 3; r++)
#pragma unroll
            for (int c = 0; c < 3; c++)
                g[r][c] = sg[r*3+c][ci][co] * C_CONV;
        float t[4][3];
#pragma unroll
        for (int c = 0; c < 3; c++){
            t[0][c] = g[0][c];
            t[1][c] = 0.5f*(g[0][c] + g[1][c] + g[2][c]);
            t[2][c] = 0.5f*(g[0][c] - g[1][c] + g[2][c]);
            t[3][c] = g[2][c];
        }
#pragma unroll
        for (int r = 0; r < 4; r++){
            float u0 = t[r][0];
            float u1 = 0.5f*(t[r][0] + t[r][1] + t[r][2]);
            float u2 = 0.5f*(t[r][0] - t[r][1] + t[r][2]);
            float u3 = t[r][2];
            int p = r*4;
            g_U[((size_t)(p+0)*256 + co0+co)*256 + ci0+ci] = __float2half_rn(u0);
            g_U[((size_t)(p+1)*256 + co0+co)*256 + ci0+ci] = __float2half_rn(u1);
            g_U[((size_t)(p+2)*256 + co0+co)*256 + ci0+ci] = __float2half_rn(u2);
            g_U[((size_t)(p+3)*256 + co0+co)*256 + ci0+ci] = __float2half_rn(u3);
        }
    }
}

// ------- winograd input transform fused with modulation: V = B^T (x*s) B ----
// grid (64, 512): x = tx, y = b*64+ty; 256 threads = ci; reads fp32 data
__global__ void vtrans(const float* __restrict__ data){
    int ci = threadIdx.x;
    int tx = blockIdx.x;
    int b = blockIdx.y >> 6, ty = blockIdx.y & 63;
    size_t t = (size_t)blockIdx.y*64 + tx;
    float sv = g_s[b*256 + ci];
    int ir0 = 2*ty - 1, ic0 = 2*tx - 1;
    float d[4][4];
#pragma unroll
    for (int r = 0; r < 4; r++){
        int ir = ir0 + r;
        bool rv = (unsigned)ir < 128u;
#pragma unroll
        for (int c = 0; c < 4; c++){
            int ic = ic0 + c;
            bool v = rv && ((unsigned)ic < 128u);
            d[r][c] = v ? data[((size_t)((b*128+ir)*128 + ic))*256 + ci] * sv : 0.f;
        }
    }
    float w[4][4];
#pragma unroll
    for (int c = 0; c < 4; c++){
        w[0][c] = d[0][c] - d[2][c];
        w[1][c] = d[1][c] + d[2][c];
        w[2][c] = d[2][c] - d[1][c];
        w[3][c] = d[1][c] - d[3][c];
    }
#pragma unroll
    for (int r = 0; r < 4; r++){
        float v0 = w[r][0] - w[r][2];
        float v1 = w[r][1] + w[r][2];
        float v2 = w[r][2] - w[r][1];
        float v3 = w[r][1] - w[r][3];
        int p = r*4;
        g_V[((size_t)(p+0)*NTILES + t)*256 + ci] = __float2half_rn(v0);
        g_V[((size_t)(p+1)*NTILES + t)*256 + ci] = __float2half_rn(v1);
        g_V[((size_t)(p+2)*NTILES + t)*256 + ci] = __float2half_rn(v2);
        g_V[((size_t)(p+3)*NTILES + t)*256 + ci] = __float2half_rn(v3);
    }
}

// ---------------- winograd output transform + epilogue ----------------------
// grid (64, 512); 256 threads = co. M aliased in g_h. Noise read gated by flag.
__global__ void otrans(const float* __restrict__ bias, const float* __restrict__ noise,
                       const float* __restrict__ ncoef){
    int co = threadIdx.x;
    int tx = blockIdx.x;
    int b = blockIdx.y >> 6, ty = blockIdx.y & 63;
    size_t t = (size_t)blockIdx.y*64 + tx;
    int nflag = g_nflag;
    float m[4][4];
#pragma unroll
    for (int p = 0; p < 16; p++)
        m[p>>2][p&3] = __half2float(g_h[((size_t)p*NTILES + t)*256 + co]);
    float z[2][4];
#pragma unroll
    for (int c = 0; c < 4; c++){
        z[0][c] = m[0][c] + m[1][c] + m[2][c];
        z[1][c] = m[1][c] - m[2][c] - m[3][c];
    }
    float dv = g_d[b*256 + co];
    float bv = bias[co];
    float cv = nflag ? ncoef[co] : 0.f;
#pragma unroll
    for (int r = 0; r < 2; r++){
        float y0 = z[r][0] + z[r][1] + z[r][2];
        float y1 = z[r][1] - z[r][2] - z[r][3];
        int row = 2*ty + r;
#pragma unroll
        for (int c = 0; c < 2; c++){
            float yv = (c == 0) ? y0 : y1;
            int col = 2*tx + c;
            size_t pix = (size_t)(b*128 + row)*128 + col;
            float o = yv*dv + bv;
            if (nflag) o += noise[pix*256 + co] * cv;
            o = lrelu(o);
            g_y[pix*256 + co] = __float2half_rn(o);
        }
    }
}

// ---------------- generic GEMM (K64, 2-stage; EPI 0=raw half, 1=D1, 2=D2) --
template<int K>
__device__ __forceinline__ void issue_gemm(Tiles* t, const __half* A, const __half* Bw,
                                           size_t m0, int n0, int s, int tid){
#pragma unroll
    for (int j = 0; j < 4; j++){
        int lin = tid + j*256;
        int r = lin >> 3, c8 = (lin & 7) * 8;
        cp16((uint32_t)__cvta_generic_to_shared(&t->A[r][c8]),
             A + (m0 + r)*(size_t)K + s*64 + c8, 16);
        cp16((uint32_t)__cvta_generic_to_shared(&t->Bt[r][c8]),
             Bw + (size_t)(n0 + r)*K + s*64 + c8, 16);
    }
}

template<int K, int N, int EPI>
__global__ void __launch_bounds__(256,2) gemm_kernel(
    const __half* __restrict__ A, const __half* __restrict__ Bw,
    const float* __restrict__ bias, void* __restrict__ outv)
{
    extern __shared__ Tiles tiles[];
    int tid = threadIdx.x;
    size_t m0 = (size_t)blockIdx.y * 128;
    int n0 = blockIdx.x * 128;
    if (EPI == 0){
        size_t z = blockIdx.z;
        A  += z * ((size_t)NTILES*256);
        Bw += z * (256*256);
        outv = (void*)((__half*)outv + z * ((size_t)NTILES*256));
    }
    int wid = tid >> 5, lane = tid & 31;
    int wm = wid >> 1, wn = wid & 1, qr = lane >> 2, qc = lane & 3;

    float acc[2][8][4];
#pragma unroll
    for (int i = 0; i < 2; i++)
#pragma unroll
        for (int j = 0; j < 8; j++)
#pragma unroll
            for (int k = 0; k < 4; k++) acc[i][j][k] = 0.f;

    const int NK = K/64;
    issue_gemm<K>(&tiles[0], A, Bw, m0, n0, 0, tid); cp_commit();
#pragma unroll 1
    for (int s = 0; s < NK; s++){
        cp_wait<0>();
        __syncthreads();
        if (s + 1 < NK){ issue_gemm<K>(&tiles[(s+1)&1], A, Bw, m0, n0, s+1, tid); cp_commit(); }
        compute_tile(tiles[s&1], acc, wm, wn, lane);
    }

#pragma unroll
    for (int mt = 0; mt < 2; mt++){
#pragma unroll
        for (int nt = 0; nt < 8; nt++){
            int col = n0 + wn*64 + nt*8 + 2*qc;
            float b0 = (EPI != 0) ? bias[col]   : 0.f;
            float b1 = (EPI != 0) ? bias[col+1] : 0.f;
#pragma unroll
            for (int r2 = 0; r2 < 2; r2++){
                size_t m = m0 + wm*32 + mt*16 + qr + r2*8;
                float v0 = acc[mt][nt][r2*2+0];
                float v1 = acc[mt][nt][r2*2+1];
                if (EPI != 0){ v0 = lrelu(v0 + b0); v1 = lrelu(v1 + b1); }
                if (EPI == 2){
                    *(float2*)((float*)outv + m*(size_t)N + col) = make_float2(v0, v1);
                } else {
                    __half2 hv = __floats2half2_rn(v0, v1);
                    *(uint32_t*)((__half*)outv + m*(size_t)N + col) = *(uint32_t*)&hv;
                }
            }
        }
    }
}

// ---------------- launch ----------------------------------------------------
extern "C" void kernel_launch(void* const* d_in, const int* in_sizes, int n_in,
                              void* d_out, int out_size){
    const float* data   = (const float*)d_in[0];
    const float* latent = (const float*)d_in[1];
    const float* noise  = (const float*)d_in[2];
    const float* stdW   = (const float*)d_in[3];
    const float* stdb   = (const float*)d_in[4];
    const float* convw  = (const float*)d_in[5];
    const float* bias   = (const float*)d_in[6];
    const float* ncoef  = (const float*)d_in[7];
    const float* d1w    = (const float*)d_in[8];
    const float* d1b    = (const float*)d_in[9];
    const float* d2w    = (const float*)d_in[10];
    const float* d2b    = (const float*)d_in[11];
    float* out = (float*)d_out;

    void *p_U, *p_V, *p_w1, *p_w2, *p_y, *p_h;
    cudaGetSymbolAddress(&p_U,  g_U);
    cudaGetSymbolAddress(&p_V,  g_V);
    cudaGetSymbolAddress(&p_w1, g_w1T);
    cudaGetSymbolAddress(&p_w2, g_w2T);
    cudaGetSymbolAddress(&p_y,  g_y);
    cudaGetSymbolAddress(&p_h,  g_h);

    int smem = (int)sizeof(Tiles) * 2;   // 73728 B
    cudaFuncSetAttribute(gemm_kernel<256,256,0>,  cudaFuncAttributeMaxDynamicSharedMemorySize, smem);
    cudaFuncSetAttribute(gemm_kernel<256,1024,1>, cudaFuncAttributeMaxDynamicSharedMemorySize, smem);
    cudaFuncSetAttribute(gemm_kernel<1024,256,2>, cudaFuncAttributeMaxDynamicSharedMemorySize, smem);

    // ncu -s 5 -c 1 profiles the 6th launch = batched winograd GEMM
    s_kernel<<<NB, CI>>>(latent, stdW, stdb);
    d_kernel<<<NB, CO>>>(convw, ncoef);
    wtrans<<<dim3(8,8), dim3(32,8)>>>(convw);
    tscale_d12<<<dim3(32,8,2), dim3(32,8)>>>(d1w, d2w, (__half*)p_w1, (__half*)p_w2);
    vtrans<<<dim3(64,512), 256>>>(data);
    gemm_kernel<256,256,0><<<dim3(2,256,16), 256, smem>>>(
        (const __half*)p_V, (const __half*)p_U, nullptr, p_h);
    otrans<<<dim3(64,512), 256>>>(bias, noise, ncoef);
    gemm_kernel<256,1024,1><<<dim3(8,1024), 256, smem>>>(
        (const __half*)p_y, (const __half*)p_w1, d1b, p_h);
    gemm_kernel<1024,256,2><<<dim3(2,1024), 256, smem>>>(
        (const __half*)p_h, (const __half*)p_w2, d2b, (void*)out);
}